// round 12
// baseline (speedup 1.0000x reference)
#include <cuda_runtime.h>
#include <cuda_fp16.h>
#include <math.h>
#include <cstdint>

// Problem constants
#define BB 4
#define LL 1024
#define DD 512
#define NN 16
#define OUTD 512
#define NLAYER 2
#define NCH 32
#define LCH 32

#define BLD (BB*LL*DD)
#define BLN (BB*LL*NN)
#define CHN (BB*NCH*DD*NN)

#define MM (BB*LL)      // 4096 rows
#define KC 1536         // concatenated K (3x512): [hi|lo|hi] x [hi|hi|lo]
#define NW 576          // widened N for fused dt+B+C gemm

// Scratch
__device__ float g_y[BLD];
__device__ float g_dt[BLD];
__device__ float g_Bm[BLN];
__device__ float g_Cm[BLN];
__device__ float g_P[CHN];
__device__ float g_He[CHN];
__device__ float g_carry[CHN];
__device__ float g_beff[DD];                      // fused decoder bias
__device__ float g_bzero[DD];                     // zero bias (zero-initialized)
__device__ __half g_Xcat0[(size_t)MM * KC];       // [Xh | Xl | Xh]
__device__ __half g_Xcat1[(size_t)MM * KC];       // z split
__device__ __half g_Wcat[5 * (size_t)NW * KC];    // [hi|hi|lo], transposed, 576-row slots

__device__ __forceinline__ float softplusf(float x) {
    return fmaxf(x, 0.f) + log1pf(__expf(-fabsf(x)));
}

__device__ __forceinline__ uint32_t smem_u32(const void* p) {
    uint32_t a;
    asm("{ .reg .u64 t; cvta.to.shared.u64 t, %1; cvt.u32.u64 %0, t; }" : "=r"(a) : "l"(p));
    return a;
}

// swizzled byte offset inside a 128B-row tile: r = row, c = 16B chunk in [0,8)
__device__ __forceinline__ uint32_t swz(int r, int c) {
    return ((uint32_t)r << 7) + ((uint32_t)(c ^ (r & 7)) << 4);
}

// ---------------------------------------------------------------------------
// fp16-input, fp32-acc HMMA GEMM. 128 threads, 4 warps, warp tile 32(M)x64(N)
// (mt=2, nt=4): per k-step 6 LDSM.x4 feed 16 MMAs -> 0.094 B/MAC.
// CTA tile 128(M) x 64(N), BK=64, 3-stage cp.async, 3 CTA/SM.
// C[M, Ncols] = Xcat[M, KC] @ Wcat[Ncols, KC]^T  (TN)
// EPI 0: bias                          grid (Ncols/64, M/128)
// EPI 1: dt softplus + Bm/Cm fused     grid (9, 32)
// EPI 2: bias + fp16-split to xout     grid (8, 32)
// ---------------------------------------------------------------------------
#define BK 64
#define STG 3
#define ABYTES 16384
#define BBYTES 8192
#define STAGE_BYTES (ABYTES + BBYTES)
#define TC_SMEM (STG * STAGE_BYTES)

template<int EPI>
__global__ void __launch_bounds__(128, 3)
tc_gemm(const __half* __restrict__ A, const __half* __restrict__ Bw,
        const float* __restrict__ bias, const float* __restrict__ bB,
        const float* __restrict__ bC, float* __restrict__ C,
        __half* __restrict__ xout)
{
    extern __shared__ char smem[];
    uint32_t sbase = smem_u32(smem);

    int tid = threadIdx.x, wid = tid >> 5, lane = tid & 31;
    int bn = blockIdx.x * 64, bm = blockIdx.y * 128;
    int wm = wid;               // m offset wm*32

    int lrow = ((lane >> 3) & 1) * 8 + (lane & 7);
    int lck = lane >> 4;
    uint32_t aoff[2][4], boff[4][4];
    #pragma unroll
    for (int mt = 0; mt < 2; mt++)
        #pragma unroll
        for (int ks = 0; ks < 4; ks++)
            aoff[mt][ks] = swz(wm * 32 + mt * 16 + lrow, ks * 2 + lck);
    #pragma unroll
    for (int nt = 0; nt < 4; nt++)
        #pragma unroll
        for (int ks = 0; ks < 4; ks++)
            boff[nt][ks] = ABYTES + swz(nt * 16 + lrow, ks * 2 + lck);

    // cp.async: A row per thread (8 chunks), B: 4 chunks per thread
    int rb = tid >> 1, cb0 = (tid & 1) * 4;
    const __half* gA = A + (size_t)(bm + tid) * KC;
    const __half* gB = Bw + (size_t)(bn + rb) * KC + cb0 * 8;
    int asel = tid & 7, bsel = rb & 7;
    uint32_t abase = (uint32_t)tid << 7;
    uint32_t bbase = ABYTES + ((uint32_t)rb << 7);

    float acc[2][8][4];
    #pragma unroll
    for (int i = 0; i < 2; i++)
        #pragma unroll
        for (int j = 0; j < 8; j++)
            #pragma unroll
            for (int q = 0; q < 4; q++) acc[i][j][q] = 0.f;

    const int NKB = KC / BK;    // 24

    #pragma unroll
    for (int s = 0; s < STG - 1; s++) {
        uint32_t st = sbase + s * STAGE_BYTES;
        int ko = s * BK;
        #pragma unroll
        for (int i = 0; i < 8; i++)
            asm volatile("cp.async.cg.shared.global [%0], [%1], 16;"
                         :: "r"(st + abase + (uint32_t)((i ^ asel) << 4)), "l"(gA + ko + i * 8));
        #pragma unroll
        for (int i = 0; i < 4; i++)
            asm volatile("cp.async.cg.shared.global [%0], [%1], 16;"
                         :: "r"(st + bbase + (uint32_t)(((cb0 + i) ^ bsel) << 4)), "l"(gB + ko + i * 8));
        asm volatile("cp.async.commit_group;" ::: "memory");
    }

    int sbuf = 0;
    for (int kb = 0; kb < NKB; kb++) {
        asm volatile("cp.async.wait_group %0;" :: "n"(STG - 2) : "memory");
        __syncthreads();

        int knext = kb + STG - 1;
        if (knext < NKB) {
            int sn = knext % STG;
            uint32_t st = sbase + sn * STAGE_BYTES;
            int ko = knext * BK;
            #pragma unroll
            for (int i = 0; i < 8; i++)
                asm volatile("cp.async.cg.shared.global [%0], [%1], 16;"
                             :: "r"(st + abase + (uint32_t)((i ^ asel) << 4)), "l"(gA + ko + i * 8));
            #pragma unroll
            for (int i = 0; i < 4; i++)
                asm volatile("cp.async.cg.shared.global [%0], [%1], 16;"
                             :: "r"(st + bbase + (uint32_t)(((cb0 + i) ^ bsel) << 4)), "l"(gB + ko + i * 8));
        }
        asm volatile("cp.async.commit_group;" ::: "memory");

        uint32_t st = sbase + sbuf * STAGE_BYTES;

        #pragma unroll
        for (int ks = 0; ks < 4; ks++) {
            uint32_t bufA[2][4], bufB[4][4];
            #pragma unroll
            for (int mt = 0; mt < 2; mt++)
                asm volatile("ldmatrix.sync.aligned.m8n8.x4.shared.b16 {%0,%1,%2,%3}, [%4];"
                             : "=r"(bufA[mt][0]), "=r"(bufA[mt][1]),
                               "=r"(bufA[mt][2]), "=r"(bufA[mt][3])
                             : "r"(st + aoff[mt][ks]));
            #pragma unroll
            for (int nt = 0; nt < 4; nt++)
                asm volatile("ldmatrix.sync.aligned.m8n8.x4.shared.b16 {%0,%1,%2,%3}, [%4];"
                             : "=r"(bufB[nt][0]), "=r"(bufB[nt][1]),
                               "=r"(bufB[nt][2]), "=r"(bufB[nt][3])
                             : "r"(st + boff[nt][ks]));
            #pragma unroll
            for (int mt = 0; mt < 2; mt++)
                #pragma unroll
                for (int nt = 0; nt < 4; nt++)
                    #pragma unroll
                    for (int nf = 0; nf < 2; nf++)
                        asm volatile(
                            "mma.sync.aligned.m16n8k16.row.col.f32.f16.f16.f32 "
                            "{%0,%1,%2,%3}, {%4,%5,%6,%7}, {%8,%9}, {%0,%1,%2,%3};"
                            : "+f"(acc[mt][nt * 2 + nf][0]), "+f"(acc[mt][nt * 2 + nf][1]),
                              "+f"(acc[mt][nt * 2 + nf][2]), "+f"(acc[mt][nt * 2 + nf][3])
                            : "r"(bufA[mt][0]), "r"(bufA[mt][1]),
                              "r"(bufA[mt][2]), "r"(bufA[mt][3]),
                              "r"(bufB[nt][nf]), "r"(bufB[nt][2 + nf]));
        }
        sbuf++;
        if (sbuf == STG) sbuf = 0;
    }

    // epilogue
    int mbase = bm + wm * 32 + (lane >> 2);
    int nbase = bn + (lane & 3) * 2;
    #pragma unroll
    for (int mt = 0; mt < 2; mt++) {
        #pragma unroll
        for (int jf = 0; jf < 8; jf++) {
            int col = nbase + (jf >> 1) * 16 + (jf & 1) * 8;
            int m0 = mbase + mt * 16;
            float b0, b1;
            if (EPI == 1 && col >= 512) {
                if (col < 528)      { b0 = bB[col - 512]; b1 = bB[col - 511]; }
                else if (col < 544) { b0 = bC[col - 528]; b1 = bC[col - 527]; }
                else                { b0 = 0.f; b1 = 0.f; }
            } else {
                b0 = bias[col]; b1 = bias[col + 1];
            }
            float v0 = acc[mt][jf][0] + b0, v1 = acc[mt][jf][1] + b1;
            float v2 = acc[mt][jf][2] + b0, v3 = acc[mt][jf][3] + b1;

            if (EPI == 1 && col >= 512) {
                if (col < 528) {
                    int n = col - 512;
                    *(float2*)(g_Bm + (size_t)m0 * NN + n)       = make_float2(v0, v1);
                    *(float2*)(g_Bm + (size_t)(m0 + 8) * NN + n) = make_float2(v2, v3);
                } else if (col < 544) {
                    int n = col - 528;
                    *(float2*)(g_Cm + (size_t)m0 * NN + n)       = make_float2(v0, v1);
                    *(float2*)(g_Cm + (size_t)(m0 + 8) * NN + n) = make_float2(v2, v3);
                }
                continue;
            }
            if (EPI == 1) { v0 = softplusf(v0); v1 = softplusf(v1); v2 = softplusf(v2); v3 = softplusf(v3); }
            *(float2*)(C + (size_t)m0 * DD + col)       = make_float2(v0, v1);
            *(float2*)(C + (size_t)(m0 + 8) * DD + col) = make_float2(v2, v3);
            if (EPI == 2) {
                __half h0 = __float2half_rn(v0), h1 = __float2half_rn(v1);
                __half h2 = __float2half_rn(v2), h3 = __float2half_rn(v3);
                __half2 hv0(h0, h1), hv1(h2, h3);
                __half2 lv0(__float2half_rn(v0 - __half2float(h0)),
                            __float2half_rn(v1 - __half2float(h1)));
                __half2 lv1(__float2half_rn(v2 - __half2float(h2)),
                            __float2half_rn(v3 - __half2float(h3)));
                __half* r0 = xout + (size_t)m0 * KC + col;
                __half* r1 = xout + (size_t)(m0 + 8) * KC + col;
                *(__half2*)(r0)        = hv0;
                *(__half2*)(r0 + 512)  = lv0;
                *(__half2*)(r0 + 1024) = hv0;
                *(__half2*)(r1)        = hv1;
                *(__half2*)(r1 + 512)  = lv1;
                *(__half2*)(r1 + 1024) = hv1;
            }
        }
    }
}

// ---------------------------------------------------------------------------
// Activation split: float [M][512] -> out fp16 [M][1536] = [hi|lo|hi]
// ---------------------------------------------------------------------------
__global__ void splitx_k(const float4* __restrict__ in, __half* __restrict__ out)
{
    int i = blockIdx.x * blockDim.x + threadIdx.x;
    int m = i >> 7;
    int k4 = (i & 127) << 2;
    float4 v = in[i];
    __half2 h0(__float2half_rn(v.x), __float2half_rn(v.y));
    __half2 h1(__float2half_rn(v.z), __float2half_rn(v.w));
    __half2 l0(__float2half_rn(v.x - __half2float(h0.x)),
               __float2half_rn(v.y - __half2float(h0.y)));
    __half2 l1(__float2half_rn(v.z - __half2float(h1.x)),
               __float2half_rn(v.w - __half2float(h1.y)));
    __half* row = out + (size_t)m * KC;
    *(__half2*)(row + k4)        = h0;
    *(__half2*)(row + k4 + 2)    = h1;
    *(__half2*)(row + k4 + 512)  = l0;
    *(__half2*)(row + k4 + 514)  = l1;
    *(__half2*)(row + k4 + 1024) = h0;
    *(__half2*)(row + k4 + 1026) = h1;
}

// ---------------------------------------------------------------------------
// Big-weight transpose+split. blockIdx.z in {0,1,2,3} -> slots {0,1,2,4}.
// slots: 0,1 = Wdt layers; 2 = Wlin layer 0; 4 = Wdec (temp, becomes F)
// ---------------------------------------------------------------------------
__global__ void tsplit_all_k(const float* __restrict__ Wdt, const float* __restrict__ Wlin,
                             const float* __restrict__ Wdec)
{
    __shared__ float t[32][33];
    int z = blockIdx.z;
    const float* W = (z == 0) ? Wdt
                   : (z == 1) ? Wdt + (size_t)DD * DD
                   : (z == 2) ? Wlin
                              : Wdec;
    int slot = (z == 3) ? 4 : z;
    __half* out = g_Wcat + (size_t)slot * NW * KC;

    int bk = blockIdx.x * 32, bn = blockIdx.y * 32;
    int tx = threadIdx.x, ty = threadIdx.y;
    #pragma unroll
    for (int i = 0; i < 32; i += 8)
        t[ty + i][tx] = W[(size_t)(bk + ty + i) * DD + bn + tx];
    __syncthreads();
    #pragma unroll
    for (int i = 0; i < 32; i += 8) {
        float v = t[tx][ty + i];
        __half h = __float2half_rn(v);
        __half l = __float2half_rn(v - __half2float(h));
        size_t o = (size_t)(bn + ty + i) * KC + bk + tx;
        out[o]        = h;
        out[o + 512]  = h;
        out[o + 1024] = l;
    }
}

// Single-slot transpose+split (for the fused decoder weight F in g_y).
__global__ void tsplit_one_k(const float* __restrict__ W, __half* __restrict__ out)
{
    __shared__ float t[32][33];
    int bk = blockIdx.x * 32, bn = blockIdx.y * 32;
    int tx = threadIdx.x, ty = threadIdx.y;
    #pragma unroll
    for (int i = 0; i < 32; i += 8)
        t[ty + i][tx] = W[(size_t)(bk + ty + i) * DD + bn + tx];
    __syncthreads();
    #pragma unroll
    for (int i = 0; i < 32; i += 8) {
        float v = t[tx][ty + i];
        __half h = __float2half_rn(v);
        __half l = __float2half_rn(v - __half2float(h));
        size_t o = (size_t)(bn + ty + i) * KC + bk + tx;
        out[o]        = h;
        out[o + 512]  = h;
        out[o + 1024] = l;
    }
}

// ---------------------------------------------------------------------------
// WB/WC transpose+split into rows 512..575 of dt slots.
// ---------------------------------------------------------------------------
__global__ void tsplit_bc_k(const float* __restrict__ WB, const float* __restrict__ WC)
{
    int l = blockIdx.y;
    int bk = blockIdx.x * 32;
    int tx = threadIdx.x;
    __half* out = g_Wcat + (size_t)l * NW * KC + (size_t)512 * KC;

    for (int r = threadIdx.y; r < 64; r += 8) {
        float v = 0.f;
        if (r < 16)      v = WB[(size_t)l * DD * NN + (size_t)(bk + tx) * NN + r];
        else if (r < 32) v = WC[(size_t)l * DD * NN + (size_t)(bk + tx) * NN + (r - 16)];
        __half h = __float2half_rn(v);
        __half lo = __float2half_rn(v - __half2float(h));
        size_t o = (size_t)r * KC + bk + tx;
        out[o]        = h;
        out[o + 512]  = h;
        out[o + 1024] = lo;
    }
}

// ---------------------------------------------------------------------------
// Fused decoder bias: beff[o] = bdec[o] + sum_d blin2[d] * Wdec[d][o]
// grid 64, block 256: 8 outputs/block, 32-way d-split per output.
// ---------------------------------------------------------------------------
__global__ void beff_k(const float* __restrict__ blin2, const float* __restrict__ Wdec,
                       const float* __restrict__ bdec)
{
    __shared__ float part[32][8];
    int og = threadIdx.x & 7;
    int r  = threadIdx.x >> 3;          // 0..31
    int o  = blockIdx.x * 8 + og;
    float acc = 0.f;
    int d0 = r * 16;
    #pragma unroll
    for (int d = d0; d < d0 + 16; d++)
        acc = fmaf(blin2[d], Wdec[(size_t)d * DD + o], acc);
    part[r][og] = acc;
    __syncthreads();
    if (threadIdx.x < 8) {
        float s = bdec[blockIdx.x * 8 + threadIdx.x];
        #pragma unroll
        for (int i = 0; i < 32; i++) s += part[i][threadIdx.x];
        g_beff[blockIdx.x * 8 + threadIdx.x] = s;
    }
}

// ---------------------------------------------------------------------------
// Scan pass 1: local chunk scan from zero; store P, He.
// grid = (4, NCH, 4), block 128
// ---------------------------------------------------------------------------
__global__ void scan1_k(const float* __restrict__ yin, const float* __restrict__ A)
{
    __shared__ float sB[LCH * NN];
    int d = blockIdx.x * 128 + threadIdx.x;
    int c = blockIdx.y, b = blockIdx.z;
    int t0 = c * LCH;

    const float4* src = (const float4*)(g_Bm + ((size_t)b * LL + t0) * NN);
    #pragma unroll
    for (int i = threadIdx.x; i < LCH * NN / 4; i += 128)
        ((float4*)sB)[i] = src[i];
    __syncthreads();

    float av[NN], h[NN], p[NN];
    #pragma unroll
    for (int q = 0; q < 4; q++)
        *(float4*)(av + q * 4) = *(const float4*)(A + (size_t)d * NN + q * 4);
    #pragma unroll
    for (int n = 0; n < NN; n++) { h[n] = 0.f; p[n] = 1.f; }

    const float* dtp = g_dt + ((size_t)b * LL + t0) * DD + d;
    const float* yp  = yin  + ((size_t)b * LL + t0) * DD + d;

    for (int t = 0; t < LCH; t++) {
        float dv = dtp[(size_t)t * DD];
        float u  = dv * yp[(size_t)t * DD];
        #pragma unroll
        for (int n = 0; n < NN; n++) {
            float e = __expf(dv * av[n]);
            p[n] *= e;
            h[n] = fmaf(e, h[n], u * sB[t * NN + n]);
        }
    }

    size_t o = (((size_t)b * NCH + c) * DD + d) * NN;
    #pragma unroll
    for (int q = 0; q < 4; q++) {
        *(float4*)(g_P  + o + q * 4) = *(float4*)(p + q * 4);
        *(float4*)(g_He + o + q * 4) = *(float4*)(h + q * 4);
    }
}

// ---------------------------------------------------------------------------
// Scan pass 2 (batched loads across NCH chunks)
// ---------------------------------------------------------------------------
__global__ void scan2_k()
{
    int tid = blockIdx.x * blockDim.x + threadIdx.x;
    int b  = tid >> 13;
    int dn = tid & 8191;
    size_t base = (size_t)b * NCH * DD * NN + dn;

    float p[NCH], he[NCH];
    #pragma unroll
    for (int c = 0; c < NCH; c++) {
        p[c]  = g_P [base + (size_t)c * DD * NN];
        he[c] = g_He[base + (size_t)c * DD * NN];
    }
    float hc = 0.f;
    float cr[NCH];
    #pragma unroll
    for (int c = 0; c < NCH; c++) {
        cr[c] = hc;
        hc = fmaf(p[c], hc, he[c]);
    }
    #pragma unroll
    for (int c = 0; c < NCH; c++)
        g_carry[base + (size_t)c * DD * NN] = cr[c];
}

// ---------------------------------------------------------------------------
// Scan pass 3: rescan with carry; write z as fp16 split into Xcat1.
// grid = (4, NCH, 4), block 128
// ---------------------------------------------------------------------------
__global__ void scan3_k(const float* __restrict__ yin, const float* __restrict__ A,
                        const float* __restrict__ Dskip)
{
    __shared__ float sB[LCH * NN];
    __shared__ float sC[LCH * NN];
    int d = blockIdx.x * 128 + threadIdx.x;
    int c = blockIdx.y, b = blockIdx.z;
    int t0 = c * LCH;

    {
        const float4* srcB = (const float4*)(g_Bm + ((size_t)b * LL + t0) * NN);
        const float4* srcC = (const float4*)(g_Cm + ((size_t)b * LL + t0) * NN);
        #pragma unroll
        for (int i = threadIdx.x; i < LCH * NN / 4; i += 128) {
            ((float4*)sB)[i] = srcB[i];
            ((float4*)sC)[i] = srcC[i];
        }
    }
    __syncthreads();

    float av[NN], h[NN];
    #pragma unroll
    for (int q = 0; q < 4; q++)
        *(float4*)(av + q * 4) = *(const float4*)(A + (size_t)d * NN + q * 4);
    size_t co = (((size_t)b * NCH + c) * DD + d) * NN;
    #pragma unroll
    for (int q = 0; q < 4; q++)
        *(float4*)(h + q * 4) = *(const float4*)(g_carry + co + q * 4);

    float ds = Dskip[d];
    const float* dtp = g_dt + ((size_t)b * LL + t0) * DD + d;
    const float* yp  = yin  + ((size_t)b * LL + t0) * DD + d;
    __half* zb = g_Xcat1 + ((size_t)b * LL + t0) * KC + d;

    for (int t = 0; t < LCH; t++) {
        float dv = dtp[(size_t)t * DD];
        float yv = yp[(size_t)t * DD];
        float u  = dv * yv;
        float acc = 0.f;
        #pragma unroll
        for (int n = 0; n < NN; n++) {
            float e = __expf(dv * av[n]);
            h[n] = fmaf(e, h[n], u * sB[t * NN + n]);
            acc = fmaf(h[n], sC[t * NN + n], acc);
        }
        float z = fmaxf(fmaf(ds, yv, acc), 0.f);
        __half hi = __float2half_rn(z);
        __half lo = __float2half_rn(z - __half2float(hi));
        __half* zr = zb + (size_t)t * KC;
        zr[0]    = hi;
        zr[512]  = lo;
        zr[1024] = hi;
    }
}

// ---------------------------------------------------------------------------
// Host launcher
// ---------------------------------------------------------------------------
extern "C" void kernel_launch(void* const* d_in, const int* in_sizes, int n_in,
                              void* d_out, int out_size)
{
    const float* x     = (const float*)d_in[0];
    const float* A     = (const float*)d_in[1];
    const float* Dskip = (const float*)d_in[2];
    const float* WB    = (const float*)d_in[3];
    const float* bB    = (const float*)d_in[4];
    const float* WC    = (const float*)d_in[5];
    const float* bC    = (const float*)d_in[6];
    const float* Wdt   = (const float*)d_in[7];
    const float* bdt   = (const float*)d_in[8];
    const float* Wlin  = (const float*)d_in[9];
    const float* blin  = (const float*)d_in[10];
    const float* Wdec  = (const float*)d_in[11];
    const float* bdec  = (const float*)d_in[12];
    float* out = (float*)d_out;

    float *py, *pdt, *pbeff, *pbzero;
    __half *px0, *px1, *pwc;
    cudaGetSymbolAddress((void**)&py,     g_y);
    cudaGetSymbolAddress((void**)&pdt,    g_dt);
    cudaGetSymbolAddress((void**)&pbeff,  g_beff);
    cudaGetSymbolAddress((void**)&pbzero, g_bzero);
    cudaGetSymbolAddress((void**)&px0,    g_Xcat0);
    cudaGetSymbolAddress((void**)&px1,    g_Xcat1);
    cudaGetSymbolAddress((void**)&pwc,    g_Wcat);

    cudaFuncSetAttribute(tc_gemm<0>, cudaFuncAttributeMaxDynamicSharedMemorySize, TC_SMEM);
    cudaFuncSetAttribute(tc_gemm<1>, cudaFuncAttributeMaxDynamicSharedMemorySize, TC_SMEM);
    cudaFuncSetAttribute(tc_gemm<2>, cudaFuncAttributeMaxDynamicSharedMemorySize, TC_SMEM);

    const size_t WCSZ = (size_t)NW * KC;
    const size_t WSZ  = (size_t)DD * DD;

    dim3 tgrid(16, 16, 4), tblk(32, 8);
    dim3 t1grid(16, 16);
    tsplit_all_k<<<tgrid, tblk>>>(Wdt, Wlin, Wdec);     // slots 0,1,2,4
    tsplit_bc_k<<<dim3(16, 2), tblk>>>(WB, WC);

    // --- Precompute fused decoder: F = Wlin2 @ Wdec (fp16 3-term), slot 4 ---
    splitx_k<<<(DD * DD / 4) / 256, 256>>>((const float4*)(Wlin + WSZ), px0);
    beff_k<<<64, 256>>>(blin + DD, Wdec, bdec);
    tc_gemm<0><<<dim3(8, 4), 128, TC_SMEM>>>(px0, pwc + 4 * WCSZ, pbzero,
                                             nullptr, nullptr, py, nullptr);
    tsplit_one_k<<<t1grid, tblk>>>(py, pwc + 4 * WCSZ);

    // --- Main pipeline ---
    dim3 gG1(NW / 64, MM / 128);   // (9, 32) fused dt+BC
    dim3 gG(DD / 64, MM / 128);    // (8, 32)
    dim3 gs(DD / 128, NCH, BB);

    splitx_k<<<(BLD / 4) / 256, 256>>>((const float4*)x, px0);

    // Layer 0
    tc_gemm<1><<<gG1, 128, TC_SMEM>>>(px0, pwc + 0 * WCSZ, bdt,
                                      bB, bC, pdt, nullptr);
    scan1_k<<<gs, 128>>>(x, A);
    scan2_k<<<(BB * DD * NN) / 256, 256>>>();
    scan3_k<<<gs, 128>>>(x, A, Dskip);
    tc_gemm<2><<<gG, 128, TC_SMEM>>>(px1, pwc + 2 * WCSZ, blin,
                                     nullptr, nullptr, py, px0);

    // Layer 1
    tc_gemm<1><<<gG1, 128, TC_SMEM>>>(px0, pwc + 1 * WCSZ, bdt + DD,
                                      bB + NN, bC + NN, pdt, nullptr);
    scan1_k<<<gs, 128>>>(py, A + (size_t)DD * NN);
    scan2_k<<<(BB * DD * NN) / 256, 256>>>();
    scan3_k<<<gs, 128>>>(py, A + (size_t)DD * NN, Dskip + DD);

    // Fused lin2+dec: out = z2 @ F + beff
    tc_gemm<0><<<gG, 128, TC_SMEM>>>(px1, pwc + 4 * WCSZ, pbeff,
                                     nullptr, nullptr, out, nullptr);
}

// round 13
// speedup vs baseline: 1.5787x; 1.5787x over previous
#include <cuda_runtime.h>
#include <cuda_fp16.h>
#include <math.h>
#include <cstdint>

// Problem constants
#define BB 4
#define LL 1024
#define DD 512
#define NN 16
#define OUTD 512
#define NLAYER 2
#define NCH 32
#define LCH 32

#define BLD (BB*LL*DD)
#define BLN (BB*LL*NN)
#define CHN (BB*NCH*DD*NN)

#define MM (BB*LL)      // 4096 rows
#define KC 1024         // concatenated K (2x512): [Xh|Xl] x [Wh|Wh]
#define NW 576          // widened N for fused dt+B+C gemm

// Scratch
__device__ float g_y[BLD];
__device__ float g_dt[BLD];
__device__ float g_Bm[BLN];
__device__ float g_Cm[BLN];
__device__ float g_P[CHN];
__device__ float g_He[CHN];
__device__ float g_carry[CHN];
__device__ float g_beff[DD];                      // fused decoder bias
__device__ float g_bzero[DD];                     // zero bias (zero-initialized)
__device__ __half g_Xcat0[(size_t)MM * KC];       // [Xh | Xl]
__device__ __half g_Xcat1[(size_t)MM * KC];       // z split
__device__ __half g_Wcat[5 * (size_t)NW * KC];    // [Wh | Wh], transposed, 576-row slots

__device__ __forceinline__ float softplusf(float x) {
    return fmaxf(x, 0.f) + log1pf(__expf(-fabsf(x)));
}

__device__ __forceinline__ uint32_t smem_u32(const void* p) {
    uint32_t a;
    asm("{ .reg .u64 t; cvta.to.shared.u64 t, %1; cvt.u32.u64 %0, t; }" : "=r"(a) : "l"(p));
    return a;
}

// swizzled byte offset inside a 128B-row tile: r = row, c = 16B chunk in [0,8)
__device__ __forceinline__ uint32_t swz(int r, int c) {
    return ((uint32_t)r << 7) + ((uint32_t)(c ^ (r & 7)) << 4);
}

// ---------------------------------------------------------------------------
// fp16-input, fp32-acc HMMA GEMM (R8/R11 configuration — best known).
// C[M, Ncols] = Xcat[M, KC] @ Wcat[Ncols, KC]^T  (TN)
// Tile 128(M) x 64(N), BK=64, 3-stage cp.async, 256 thr (4M x 2N warps).
// EPI 0: bias                          grid (Ncols/64, M/128)
// EPI 1: dt softplus + Bm/Cm fused     grid (9, 32)
// EPI 2: bias + fp16-split to xout     grid (8, 32)
// ---------------------------------------------------------------------------
#define BK 64
#define STG 3
#define ABYTES 16384
#define BBYTES 8192
#define STAGE_BYTES (ABYTES + BBYTES)
#define TC_SMEM (STG * STAGE_BYTES)

template<int EPI>
__global__ void __launch_bounds__(256, 3)
tc_gemm(const __half* __restrict__ A, const __half* __restrict__ Bw,
        const float* __restrict__ bias, const float* __restrict__ bB,
        const float* __restrict__ bC, float* __restrict__ C,
        __half* __restrict__ xout)
{
    extern __shared__ char smem[];
    uint32_t sbase = smem_u32(smem);

    int tid = threadIdx.x, wid = tid >> 5, lane = tid & 31;
    int bn = blockIdx.x * 64, bm = blockIdx.y * 128;
    int wm = wid & 3;           // m offset wm*32
    int wn = wid >> 2;          // n offset wn*32

    int lrow = ((lane >> 3) & 1) * 8 + (lane & 7);
    int lck = lane >> 4;
    uint32_t aoff[2][4], boff[2][4];
    #pragma unroll
    for (int mt = 0; mt < 2; mt++)
        #pragma unroll
        for (int ks = 0; ks < 4; ks++)
            aoff[mt][ks] = swz(wm * 32 + mt * 16 + lrow, ks * 2 + lck);
    #pragma unroll
    for (int nt = 0; nt < 2; nt++)
        #pragma unroll
        for (int ks = 0; ks < 4; ks++)
            boff[nt][ks] = ABYTES + swz(wn * 32 + nt * 16 + lrow, ks * 2 + lck);

    int ra = tid >> 1, ca0 = (tid & 1) * 4;
    int rb = tid >> 2, cb0 = (tid & 3) * 2;
    const __half* gA = A + (size_t)(bm + ra) * KC + ca0 * 8;
    const __half* gB = Bw + (size_t)(bn + rb) * KC + cb0 * 8;
    uint32_t dA[4], dB[2];
    #pragma unroll
    for (int i = 0; i < 4; i++) dA[i] = swz(ra, ca0 + i);
    #pragma unroll
    for (int i = 0; i < 2; i++) dB[i] = ABYTES + swz(rb, cb0 + i);

    float acc[2][4][4];
    #pragma unroll
    for (int i = 0; i < 2; i++)
        #pragma unroll
        for (int j = 0; j < 4; j++)
            #pragma unroll
            for (int q = 0; q < 4; q++) acc[i][j][q] = 0.f;

    const int NKB = KC / BK;    // 16

    #pragma unroll
    for (int s = 0; s < STG - 1; s++) {
        uint32_t st = sbase + s * STAGE_BYTES;
        int ko = s * BK;
        #pragma unroll
        for (int i = 0; i < 4; i++)
            asm volatile("cp.async.cg.shared.global [%0], [%1], 16;" :: "r"(st + dA[i]), "l"(gA + ko + i * 8));
        #pragma unroll
        for (int i = 0; i < 2; i++)
            asm volatile("cp.async.cg.shared.global [%0], [%1], 16;" :: "r"(st + dB[i]), "l"(gB + ko + i * 8));
        asm volatile("cp.async.commit_group;" ::: "memory");
    }

    uint32_t bufA[2][2][4], bufB[2][2][4];

    int sbuf = 0;
    for (int kb = 0; kb < NKB; kb++) {
        asm volatile("cp.async.wait_group %0;" :: "n"(STG - 2) : "memory");
        __syncthreads();

        int knext = kb + STG - 1;
        if (knext < NKB) {
            int sn = knext % STG;
            uint32_t st = sbase + sn * STAGE_BYTES;
            int ko = knext * BK;
            #pragma unroll
            for (int i = 0; i < 4; i++)
                asm volatile("cp.async.cg.shared.global [%0], [%1], 16;" :: "r"(st + dA[i]), "l"(gA + ko + i * 8));
            #pragma unroll
            for (int i = 0; i < 2; i++)
                asm volatile("cp.async.cg.shared.global [%0], [%1], 16;" :: "r"(st + dB[i]), "l"(gB + ko + i * 8));
        }
        asm volatile("cp.async.commit_group;" ::: "memory");

        uint32_t st = sbase + sbuf * STAGE_BYTES;

        // prime ks=0 operands
        #pragma unroll
        for (int mt = 0; mt < 2; mt++)
            asm volatile("ldmatrix.sync.aligned.m8n8.x4.shared.b16 {%0,%1,%2,%3}, [%4];"
                         : "=r"(bufA[0][mt][0]), "=r"(bufA[0][mt][1]),
                           "=r"(bufA[0][mt][2]), "=r"(bufA[0][mt][3])
                         : "r"(st + aoff[mt][0]));
        #pragma unroll
        for (int nt = 0; nt < 2; nt++)
            asm volatile("ldmatrix.sync.aligned.m8n8.x4.shared.b16 {%0,%1,%2,%3}, [%4];"
                         : "=r"(bufB[0][nt][0]), "=r"(bufB[0][nt][1]),
                           "=r"(bufB[0][nt][2]), "=r"(bufB[0][nt][3])
                         : "r"(st + boff[nt][0]));

        #pragma unroll
        for (int ks = 0; ks < 4; ks++) {
            int cb = ks & 1, nb = cb ^ 1;
            if (ks < 3) {
                #pragma unroll
                for (int mt = 0; mt < 2; mt++)
                    asm volatile("ldmatrix.sync.aligned.m8n8.x4.shared.b16 {%0,%1,%2,%3}, [%4];"
                                 : "=r"(bufA[nb][mt][0]), "=r"(bufA[nb][mt][1]),
                                   "=r"(bufA[nb][mt][2]), "=r"(bufA[nb][mt][3])
                                 : "r"(st + aoff[mt][ks + 1]));
                #pragma unroll
                for (int nt = 0; nt < 2; nt++)
                    asm volatile("ldmatrix.sync.aligned.m8n8.x4.shared.b16 {%0,%1,%2,%3}, [%4];"
                                 : "=r"(bufB[nb][nt][0]), "=r"(bufB[nb][nt][1]),
                                   "=r"(bufB[nb][nt][2]), "=r"(bufB[nb][nt][3])
                                 : "r"(st + boff[nt][ks + 1]));
            }
            #pragma unroll
            for (int mt = 0; mt < 2; mt++)
                #pragma unroll
                for (int nt = 0; nt < 2; nt++)
                    #pragma unroll
                    for (int nf = 0; nf < 2; nf++)
                        asm volatile(
                            "mma.sync.aligned.m16n8k16.row.col.f32.f16.f16.f32 "
                            "{%0,%1,%2,%3}, {%4,%5,%6,%7}, {%8,%9}, {%0,%1,%2,%3};"
                            : "+f"(acc[mt][nt * 2 + nf][0]), "+f"(acc[mt][nt * 2 + nf][1]),
                              "+f"(acc[mt][nt * 2 + nf][2]), "+f"(acc[mt][nt * 2 + nf][3])
                            : "r"(bufA[cb][mt][0]), "r"(bufA[cb][mt][1]),
                              "r"(bufA[cb][mt][2]), "r"(bufA[cb][mt][3]),
                              "r"(bufB[cb][nt][nf]), "r"(bufB[cb][nt][2 + nf]));
        }
        sbuf++;
        if (sbuf == STG) sbuf = 0;
    }

    // epilogue
    int mbase = bm + wm * 32 + (lane >> 2);
    int nbase = bn + wn * 32 + (lane & 3) * 2;
    #pragma unroll
    for (int mt = 0; mt < 2; mt++) {
        #pragma unroll
        for (int jf = 0; jf < 4; jf++) {
            int col = nbase + (jf >> 1) * 16 + (jf & 1) * 8;
            int m0 = mbase + mt * 16;
            float b0, b1;
            if (EPI == 1 && col >= 512) {
                if (col < 528)      { b0 = bB[col - 512]; b1 = bB[col - 511]; }
                else if (col < 544) { b0 = bC[col - 528]; b1 = bC[col - 527]; }
                else                { b0 = 0.f; b1 = 0.f; }
            } else {
                b0 = bias[col]; b1 = bias[col + 1];
            }
            float v0 = acc[mt][jf][0] + b0, v1 = acc[mt][jf][1] + b1;
            float v2 = acc[mt][jf][2] + b0, v3 = acc[mt][jf][3] + b1;

            if (EPI == 1 && col >= 512) {
                if (col < 528) {
                    int n = col - 512;
                    *(float2*)(g_Bm + (size_t)m0 * NN + n)       = make_float2(v0, v1);
                    *(float2*)(g_Bm + (size_t)(m0 + 8) * NN + n) = make_float2(v2, v3);
                } else if (col < 544) {
                    int n = col - 528;
                    *(float2*)(g_Cm + (size_t)m0 * NN + n)       = make_float2(v0, v1);
                    *(float2*)(g_Cm + (size_t)(m0 + 8) * NN + n) = make_float2(v2, v3);
                }
                continue;
            }
            if (EPI == 1) { v0 = softplusf(v0); v1 = softplusf(v1); v2 = softplusf(v2); v3 = softplusf(v3); }
            *(float2*)(C + (size_t)m0 * DD + col)       = make_float2(v0, v1);
            *(float2*)(C + (size_t)(m0 + 8) * DD + col) = make_float2(v2, v3);
            if (EPI == 2) {
                __half h0 = __float2half_rn(v0), h1 = __float2half_rn(v1);
                __half h2 = __float2half_rn(v2), h3 = __float2half_rn(v3);
                __half2 hv0(h0, h1), hv1(h2, h3);
                __half2 lv0(__float2half_rn(v0 - __half2float(h0)),
                            __float2half_rn(v1 - __half2float(h1)));
                __half2 lv1(__float2half_rn(v2 - __half2float(h2)),
                            __float2half_rn(v3 - __half2float(h3)));
                __half* r0 = xout + (size_t)m0 * KC + col;
                __half* r1 = xout + (size_t)(m0 + 8) * KC + col;
                *(__half2*)(r0)        = hv0;
                *(__half2*)(r0 + 512)  = lv0;
                *(__half2*)(r1)        = hv1;
                *(__half2*)(r1 + 512)  = lv1;
            }
        }
    }
}

// ---------------------------------------------------------------------------
// Activation split: float [M][512] -> out fp16 [M][1024] = [hi|lo]
// ---------------------------------------------------------------------------
__global__ void splitx_k(const float4* __restrict__ in, __half* __restrict__ out)
{
    int i = blockIdx.x * blockDim.x + threadIdx.x;
    int m = i >> 7;
    int k4 = (i & 127) << 2;
    float4 v = in[i];
    __half2 h0(__float2half_rn(v.x), __float2half_rn(v.y));
    __half2 h1(__float2half_rn(v.z), __float2half_rn(v.w));
    __half2 l0(__float2half_rn(v.x - __half2float(h0.x)),
               __float2half_rn(v.y - __half2float(h0.y)));
    __half2 l1(__float2half_rn(v.z - __half2float(h1.x)),
               __float2half_rn(v.w - __half2float(h1.y)));
    __half* row = out + (size_t)m * KC;
    *(__half2*)(row + k4)       = h0;
    *(__half2*)(row + k4 + 2)   = h1;
    *(__half2*)(row + k4 + 512) = l0;
    *(__half2*)(row + k4 + 514) = l1;
}

// ---------------------------------------------------------------------------
// Big-weight transpose+split. blockIdx.z in {0,1,2,3} -> slots {0,1,2,4}.
// Weight side is [Wh|Wh] (hi duplicated; lo dropped per 2-term split).
// ---------------------------------------------------------------------------
__global__ void tsplit_all_k(const float* __restrict__ Wdt, const float* __restrict__ Wlin,
                             const float* __restrict__ Wdec)
{
    __shared__ float t[32][33];
    int z = blockIdx.z;
    const float* W = (z == 0) ? Wdt
                   : (z == 1) ? Wdt + (size_t)DD * DD
                   : (z == 2) ? Wlin
                              : Wdec;
    int slot = (z == 3) ? 4 : z;
    __half* out = g_Wcat + (size_t)slot * NW * KC;

    int bk = blockIdx.x * 32, bn = blockIdx.y * 32;
    int tx = threadIdx.x, ty = threadIdx.y;
    #pragma unroll
    for (int i = 0; i < 32; i += 8)
        t[ty + i][tx] = W[(size_t)(bk + ty + i) * DD + bn + tx];
    __syncthreads();
    #pragma unroll
    for (int i = 0; i < 32; i += 8) {
        float v = t[tx][ty + i];
        __half h = __float2half_rn(v);
        size_t o = (size_t)(bn + ty + i) * KC + bk + tx;
        out[o]       = h;
        out[o + 512] = h;
    }
}

// Single-slot transpose+split (for the fused decoder weight F in g_y).
__global__ void tsplit_one_k(const float* __restrict__ W, __half* __restrict__ out)
{
    __shared__ float t[32][33];
    int bk = blockIdx.x * 32, bn = blockIdx.y * 32;
    int tx = threadIdx.x, ty = threadIdx.y;
    #pragma unroll
    for (int i = 0; i < 32; i += 8)
        t[ty + i][tx] = W[(size_t)(bk + ty + i) * DD + bn + tx];
    __syncthreads();
    #pragma unroll
    for (int i = 0; i < 32; i += 8) {
        float v = t[tx][ty + i];
        __half h = __float2half_rn(v);
        size_t o = (size_t)(bn + ty + i) * KC + bk + tx;
        out[o]       = h;
        out[o + 512] = h;
    }
}

// ---------------------------------------------------------------------------
// WB/WC transpose+split into rows 512..575 of dt slots.
// ---------------------------------------------------------------------------
__global__ void tsplit_bc_k(const float* __restrict__ WB, const float* __restrict__ WC)
{
    int l = blockIdx.y;
    int bk = blockIdx.x * 32;
    int tx = threadIdx.x;
    __half* out = g_Wcat + (size_t)l * NW * KC + (size_t)512 * KC;

    for (int r = threadIdx.y; r < 64; r += 8) {
        float v = 0.f;
        if (r < 16)      v = WB[(size_t)l * DD * NN + (size_t)(bk + tx) * NN + r];
        else if (r < 32) v = WC[(size_t)l * DD * NN + (size_t)(bk + tx) * NN + (r - 16)];
        __half h = __float2half_rn(v);
        size_t o = (size_t)r * KC + bk + tx;
        out[o]       = h;
        out[o + 512] = h;
    }
}

// ---------------------------------------------------------------------------
// Fused decoder bias: beff[o] = bdec[o] + sum_d blin2[d] * Wdec[d][o]
// grid 64, block 256: 8 outputs/block, 32-way d-split per output.
// ---------------------------------------------------------------------------
__global__ void beff_k(const float* __restrict__ blin2, const float* __restrict__ Wdec,
                       const float* __restrict__ bdec)
{
    __shared__ float part[32][8];
    int og = threadIdx.x & 7;
    int r  = threadIdx.x >> 3;          // 0..31
    int o  = blockIdx.x * 8 + og;
    float acc = 0.f;
    int d0 = r * 16;
    #pragma unroll
    for (int d = d0; d < d0 + 16; d++)
        acc = fmaf(blin2[d], Wdec[(size_t)d * DD + o], acc);
    part[r][og] = acc;
    __syncthreads();
    if (threadIdx.x < 8) {
        float s = bdec[blockIdx.x * 8 + threadIdx.x];
        #pragma unroll
        for (int i = 0; i < 32; i++) s += part[i][threadIdx.x];
        g_beff[blockIdx.x * 8 + threadIdx.x] = s;
    }
}

// ---------------------------------------------------------------------------
// Scan pass 1: local chunk scan from zero; store P, He.
// grid = (4, NCH, 4), block 128
// ---------------------------------------------------------------------------
__global__ void scan1_k(const float* __restrict__ yin, const float* __restrict__ A)
{
    __shared__ float sB[LCH * NN];
    int d = blockIdx.x * 128 + threadIdx.x;
    int c = blockIdx.y, b = blockIdx.z;
    int t0 = c * LCH;

    const float4* src = (const float4*)(g_Bm + ((size_t)b * LL + t0) * NN);
    #pragma unroll
    for (int i = threadIdx.x; i < LCH * NN / 4; i += 128)
        ((float4*)sB)[i] = src[i];
    __syncthreads();

    float av[NN], h[NN], p[NN];
    #pragma unroll
    for (int q = 0; q < 4; q++)
        *(float4*)(av + q * 4) = *(const float4*)(A + (size_t)d * NN + q * 4);
    #pragma unroll
    for (int n = 0; n < NN; n++) { h[n] = 0.f; p[n] = 1.f; }

    const float* dtp = g_dt + ((size_t)b * LL + t0) * DD + d;
    const float* yp  = yin  + ((size_t)b * LL + t0) * DD + d;

    for (int t = 0; t < LCH; t++) {
        float dv = dtp[(size_t)t * DD];
        float u  = dv * yp[(size_t)t * DD];
        #pragma unroll
        for (int n = 0; n < NN; n++) {
            float e = __expf(dv * av[n]);
            p[n] *= e;
            h[n] = fmaf(e, h[n], u * sB[t * NN + n]);
        }
    }

    size_t o = (((size_t)b * NCH + c) * DD + d) * NN;
    #pragma unroll
    for (int q = 0; q < 4; q++) {
        *(float4*)(g_P  + o + q * 4) = *(float4*)(p + q * 4);
        *(float4*)(g_He + o + q * 4) = *(float4*)(h + q * 4);
    }
}

// ---------------------------------------------------------------------------
// Scan pass 2 (batched loads across NCH chunks)
// ---------------------------------------------------------------------------
__global__ void scan2_k()
{
    int tid = blockIdx.x * blockDim.x + threadIdx.x;
    int b  = tid >> 13;
    int dn = tid & 8191;
    size_t base = (size_t)b * NCH * DD * NN + dn;

    float p[NCH], he[NCH];
    #pragma unroll
    for (int c = 0; c < NCH; c++) {
        p[c]  = g_P [base + (size_t)c * DD * NN];
        he[c] = g_He[base + (size_t)c * DD * NN];
    }
    float hc = 0.f;
    float cr[NCH];
    #pragma unroll
    for (int c = 0; c < NCH; c++) {
        cr[c] = hc;
        hc = fmaf(p[c], hc, he[c]);
    }
    #pragma unroll
    for (int c = 0; c < NCH; c++)
        g_carry[base + (size_t)c * DD * NN] = cr[c];
}

// ---------------------------------------------------------------------------
// Scan pass 3: rescan with carry; write z as fp16 split into Xcat1.
// grid = (4, NCH, 4), block 128
// ---------------------------------------------------------------------------
__global__ void scan3_k(const float* __restrict__ yin, const float* __restrict__ A,
                        const float* __restrict__ Dskip)
{
    __shared__ float sB[LCH * NN];
    __shared__ float sC[LCH * NN];
    int d = blockIdx.x * 128 + threadIdx.x;
    int c = blockIdx.y, b = blockIdx.z;
    int t0 = c * LCH;

    {
        const float4* srcB = (const float4*)(g_Bm + ((size_t)b * LL + t0) * NN);
        const float4* srcC = (const float4*)(g_Cm + ((size_t)b * LL + t0) * NN);
        #pragma unroll
        for (int i = threadIdx.x; i < LCH * NN / 4; i += 128) {
            ((float4*)sB)[i] = srcB[i];
            ((float4*)sC)[i] = srcC[i];
        }
    }
    __syncthreads();

    float av[NN], h[NN];
    #pragma unroll
    for (int q = 0; q < 4; q++)
        *(float4*)(av + q * 4) = *(const float4*)(A + (size_t)d * NN + q * 4);
    size_t co = (((size_t)b * NCH + c) * DD + d) * NN;
    #pragma unroll
    for (int q = 0; q < 4; q++)
        *(float4*)(h + q * 4) = *(const float4*)(g_carry + co + q * 4);

    float ds = Dskip[d];
    const float* dtp = g_dt + ((size_t)b * LL + t0) * DD + d;
    const float* yp  = yin  + ((size_t)b * LL + t0) * DD + d;
    __half* zb = g_Xcat1 + ((size_t)b * LL + t0) * KC + d;

    for (int t = 0; t < LCH; t++) {
        float dv = dtp[(size_t)t * DD];
        float yv = yp[(size_t)t * DD];
        float u  = dv * yv;
        float acc = 0.f;
        #pragma unroll
        for (int n = 0; n < NN; n++) {
            float e = __expf(dv * av[n]);
            h[n] = fmaf(e, h[n], u * sB[t * NN + n]);
            acc = fmaf(h[n], sC[t * NN + n], acc);
        }
        float z = fmaxf(fmaf(ds, yv, acc), 0.f);
        __half hi = __float2half_rn(z);
        __half lo = __float2half_rn(z - __half2float(hi));
        __half* zr = zb + (size_t)t * KC;
        zr[0]   = hi;
        zr[512] = lo;
    }
}

// ---------------------------------------------------------------------------
// Host launcher
// ---------------------------------------------------------------------------
extern "C" void kernel_launch(void* const* d_in, const int* in_sizes, int n_in,
                              void* d_out, int out_size)
{
    const float* x     = (const float*)d_in[0];
    const float* A     = (const float*)d_in[1];
    const float* Dskip = (const float*)d_in[2];
    const float* WB    = (const float*)d_in[3];
    const float* bB    = (const float*)d_in[4];
    const float* WC    = (const float*)d_in[5];
    const float* bC    = (const float*)d_in[6];
    const float* Wdt   = (const float*)d_in[7];
    const float* bdt   = (const float*)d_in[8];
    const float* Wlin  = (const float*)d_in[9];
    const float* blin  = (const float*)d_in[10];
    const float* Wdec  = (const float*)d_in[11];
    const float* bdec  = (const float*)d_in[12];
    float* out = (float*)d_out;

    float *py, *pdt, *pbeff, *pbzero;
    __half *px0, *px1, *pwc;
    cudaGetSymbolAddress((void**)&py,     g_y);
    cudaGetSymbolAddress((void**)&pdt,    g_dt);
    cudaGetSymbolAddress((void**)&pbeff,  g_beff);
    cudaGetSymbolAddress((void**)&pbzero, g_bzero);
    cudaGetSymbolAddress((void**)&px0,    g_Xcat0);
    cudaGetSymbolAddress((void**)&px1,    g_Xcat1);
    cudaGetSymbolAddress((void**)&pwc,    g_Wcat);

    cudaFuncSetAttribute(tc_gemm<0>, cudaFuncAttributeMaxDynamicSharedMemorySize, TC_SMEM);
    cudaFuncSetAttribute(tc_gemm<1>, cudaFuncAttributeMaxDynamicSharedMemorySize, TC_SMEM);
    cudaFuncSetAttribute(tc_gemm<2>, cudaFuncAttributeMaxDynamicSharedMemorySize, TC_SMEM);

    const size_t WCSZ = (size_t)NW * KC;
    const size_t WSZ  = (size_t)DD * DD;

    dim3 tgrid(16, 16, 4), tblk(32, 8);
    dim3 t1grid(16, 16);
    tsplit_all_k<<<tgrid, tblk>>>(Wdt, Wlin, Wdec);     // slots 0,1,2,4
    tsplit_bc_k<<<dim3(16, 2), tblk>>>(WB, WC);

    // --- Precompute fused decoder: F = Wlin2 @ Wdec (fp16 2-term), slot 4 ---
    splitx_k<<<(DD * DD / 4) / 256, 256>>>((const float4*)(Wlin + WSZ), px0);
    beff_k<<<64, 256>>>(blin + DD, Wdec, bdec);
    tc_gemm<0><<<dim3(8, 4), 256, TC_SMEM>>>(px0, pwc + 4 * WCSZ, pbzero,
                                             nullptr, nullptr, py, nullptr);
    tsplit_one_k<<<t1grid, tblk>>>(py, pwc + 4 * WCSZ);

    // --- Main pipeline ---
    dim3 gG1(NW / 64, MM / 128);   // (9, 32) fused dt+BC
    dim3 gG(DD / 64, MM / 128);    // (8, 32)
    dim3 gs(DD / 128, NCH, BB);

    splitx_k<<<(BLD / 4) / 256, 256>>>((const float4*)x, px0);

    // Layer 0
    tc_gemm<1><<<gG1, 256, TC_SMEM>>>(px0, pwc + 0 * WCSZ, bdt,
                                      bB, bC, pdt, nullptr);
    scan1_k<<<gs, 128>>>(x, A);
    scan2_k<<<(BB * DD * NN) / 256, 256>>>();
    scan3_k<<<gs, 128>>>(x, A, Dskip);
    tc_gemm<2><<<gG, 256, TC_SMEM>>>(px1, pwc + 2 * WCSZ, blin,
                                     nullptr, nullptr, py, px0);

    // Layer 1
    tc_gemm<1><<<gG1, 256, TC_SMEM>>>(px0, pwc + 1 * WCSZ, bdt + DD,
                                      bB + NN, bC + NN, pdt, nullptr);
    scan1_k<<<gs, 128>>>(py, A + (size_t)DD * NN);
    scan2_k<<<(BB * DD * NN) / 256, 256>>>();
    scan3_k<<<gs, 128>>>(py, A + (size_t)DD * NN, Dskip + DD);

    // Fused lin2+dec: out = z2 @ F + beff
    tc_gemm<0><<<gG, 256, TC_SMEM>>>(px1, pwc + 4 * WCSZ, pbeff,
                                     nullptr, nullptr, out, nullptr);
}

// round 14
// speedup vs baseline: 1.6232x; 1.0282x over previous
#include <cuda_runtime.h>
#include <cuda_fp16.h>
#include <math.h>
#include <cstdint>

// Problem constants
#define BB 4
#define LL 1024
#define DD 512
#define NN 16
#define OUTD 512
#define NLAYER 2
#define NCH 32
#define LCH 32

#define BLD (BB*LL*DD)
#define BLN (BB*LL*NN)
#define CHN (BB*NCH*DD*NN)

#define MM (BB*LL)      // 4096 rows
#define KC 1024         // concatenated K (2x512): [Xh|Xl] x [Wh|Wh]
#define NW 576          // widened N for fused dt+B+C gemm

// Scratch
__device__ float g_y[BLD];
__device__ float g_dt[BLD];
__device__ float g_Bm[BLN];
__device__ float g_Cm[BLN];
__device__ float g_P[CHN];
__device__ float g_He[CHN];
__device__ float g_carry[CHN];
__device__ float g_beff[DD];                      // fused decoder bias
__device__ float g_bzero[DD];                     // zero bias (zero-initialized)
__device__ __half g_Xcat0[(size_t)MM * KC];       // [Xh | Xl]
__device__ __half g_Xcat1[(size_t)MM * KC];       // z split (also temp Wlin2 split)
__device__ __half g_Wcat[5 * (size_t)NW * KC];    // [Wh | Wh], transposed, 576-row slots

__device__ __forceinline__ float softplusf(float x) {
    return fmaxf(x, 0.f) + log1pf(__expf(-fabsf(x)));
}

__device__ __forceinline__ uint32_t smem_u32(const void* p) {
    uint32_t a;
    asm("{ .reg .u64 t; cvta.to.shared.u64 t, %1; cvt.u32.u64 %0, t; }" : "=r"(a) : "l"(p));
    return a;
}

// swizzled byte offset inside a 128B-row tile: r = row, c = 16B chunk in [0,8)
__device__ __forceinline__ uint32_t swz(int r, int c) {
    return ((uint32_t)r << 7) + ((uint32_t)(c ^ (r & 7)) << 4);
}

// ---------------------------------------------------------------------------
// fp16-input, fp32-acc HMMA GEMM (R8/R11 configuration — best known).
// C[M, Ncols] = Xcat[M, KC] @ Wcat[Ncols, KC]^T  (TN)
// Tile 128(M) x 64(N), BK=64, 3-stage cp.async, 256 thr (4M x 2N warps).
// EPI 0: bias                          grid (Ncols/64, M/128)
// EPI 1: dt softplus + Bm/Cm fused     grid (9, 32)
// EPI 2: bias + fp16-split to xout     grid (8, 32)
// ---------------------------------------------------------------------------
#define BK 64
#define STG 3
#define ABYTES 16384
#define BBYTES 8192
#define STAGE_BYTES (ABYTES + BBYTES)
#define TC_SMEM (STG * STAGE_BYTES)

template<int EPI>
__global__ void __launch_bounds__(256, 3)
tc_gemm(const __half* __restrict__ A, const __half* __restrict__ Bw,
        const float* __restrict__ bias, const float* __restrict__ bB,
        const float* __restrict__ bC, float* __restrict__ C,
        __half* __restrict__ xout)
{
    extern __shared__ char smem[];
    uint32_t sbase = smem_u32(smem);

    int tid = threadIdx.x, wid = tid >> 5, lane = tid & 31;
    int bn = blockIdx.x * 64, bm = blockIdx.y * 128;
    int wm = wid & 3;           // m offset wm*32
    int wn = wid >> 2;          // n offset wn*32

    int lrow = ((lane >> 3) & 1) * 8 + (lane & 7);
    int lck = lane >> 4;
    uint32_t aoff[2][4], boff[2][4];
    #pragma unroll
    for (int mt = 0; mt < 2; mt++)
        #pragma unroll
        for (int ks = 0; ks < 4; ks++)
            aoff[mt][ks] = swz(wm * 32 + mt * 16 + lrow, ks * 2 + lck);
    #pragma unroll
    for (int nt = 0; nt < 2; nt++)
        #pragma unroll
        for (int ks = 0; ks < 4; ks++)
            boff[nt][ks] = ABYTES + swz(wn * 32 + nt * 16 + lrow, ks * 2 + lck);

    int ra = tid >> 1, ca0 = (tid & 1) * 4;
    int rb = tid >> 2, cb0 = (tid & 3) * 2;
    const __half* gA = A + (size_t)(bm + ra) * KC + ca0 * 8;
    const __half* gB = Bw + (size_t)(bn + rb) * KC + cb0 * 8;
    uint32_t dA[4], dB[2];
    #pragma unroll
    for (int i = 0; i < 4; i++) dA[i] = swz(ra, ca0 + i);
    #pragma unroll
    for (int i = 0; i < 2; i++) dB[i] = ABYTES + swz(rb, cb0 + i);

    float acc[2][4][4];
    #pragma unroll
    for (int i = 0; i < 2; i++)
        #pragma unroll
        for (int j = 0; j < 4; j++)
            #pragma unroll
            for (int q = 0; q < 4; q++) acc[i][j][q] = 0.f;

    const int NKB = KC / BK;    // 16

    #pragma unroll
    for (int s = 0; s < STG - 1; s++) {
        uint32_t st = sbase + s * STAGE_BYTES;
        int ko = s * BK;
        #pragma unroll
        for (int i = 0; i < 4; i++)
            asm volatile("cp.async.cg.shared.global [%0], [%1], 16;" :: "r"(st + dA[i]), "l"(gA + ko + i * 8));
        #pragma unroll
        for (int i = 0; i < 2; i++)
            asm volatile("cp.async.cg.shared.global [%0], [%1], 16;" :: "r"(st + dB[i]), "l"(gB + ko + i * 8));
        asm volatile("cp.async.commit_group;" ::: "memory");
    }

    uint32_t bufA[2][2][4], bufB[2][2][4];

    int sbuf = 0;
    for (int kb = 0; kb < NKB; kb++) {
        asm volatile("cp.async.wait_group %0;" :: "n"(STG - 2) : "memory");
        __syncthreads();

        int knext = kb + STG - 1;
        if (knext < NKB) {
            int sn = knext % STG;
            uint32_t st = sbase + sn * STAGE_BYTES;
            int ko = knext * BK;
            #pragma unroll
            for (int i = 0; i < 4; i++)
                asm volatile("cp.async.cg.shared.global [%0], [%1], 16;" :: "r"(st + dA[i]), "l"(gA + ko + i * 8));
            #pragma unroll
            for (int i = 0; i < 2; i++)
                asm volatile("cp.async.cg.shared.global [%0], [%1], 16;" :: "r"(st + dB[i]), "l"(gB + ko + i * 8));
        }
        asm volatile("cp.async.commit_group;" ::: "memory");

        uint32_t st = sbase + sbuf * STAGE_BYTES;

        // prime ks=0 operands
        #pragma unroll
        for (int mt = 0; mt < 2; mt++)
            asm volatile("ldmatrix.sync.aligned.m8n8.x4.shared.b16 {%0,%1,%2,%3}, [%4];"
                         : "=r"(bufA[0][mt][0]), "=r"(bufA[0][mt][1]),
                           "=r"(bufA[0][mt][2]), "=r"(bufA[0][mt][3])
                         : "r"(st + aoff[mt][0]));
        #pragma unroll
        for (int nt = 0; nt < 2; nt++)
            asm volatile("ldmatrix.sync.aligned.m8n8.x4.shared.b16 {%0,%1,%2,%3}, [%4];"
                         : "=r"(bufB[0][nt][0]), "=r"(bufB[0][nt][1]),
                           "=r"(bufB[0][nt][2]), "=r"(bufB[0][nt][3])
                         : "r"(st + boff[nt][0]));

        #pragma unroll
        for (int ks = 0; ks < 4; ks++) {
            int cb = ks & 1, nb = cb ^ 1;
            if (ks < 3) {
                #pragma unroll
                for (int mt = 0; mt < 2; mt++)
                    asm volatile("ldmatrix.sync.aligned.m8n8.x4.shared.b16 {%0,%1,%2,%3}, [%4];"
                                 : "=r"(bufA[nb][mt][0]), "=r"(bufA[nb][mt][1]),
                                   "=r"(bufA[nb][mt][2]), "=r"(bufA[nb][mt][3])
                                 : "r"(st + aoff[mt][ks + 1]));
                #pragma unroll
                for (int nt = 0; nt < 2; nt++)
                    asm volatile("ldmatrix.sync.aligned.m8n8.x4.shared.b16 {%0,%1,%2,%3}, [%4];"
                                 : "=r"(bufB[nb][nt][0]), "=r"(bufB[nb][nt][1]),
                                   "=r"(bufB[nb][nt][2]), "=r"(bufB[nb][nt][3])
                                 : "r"(st + boff[nt][ks + 1]));
            }
            #pragma unroll
            for (int mt = 0; mt < 2; mt++)
                #pragma unroll
                for (int nt = 0; nt < 2; nt++)
                    #pragma unroll
                    for (int nf = 0; nf < 2; nf++)
                        asm volatile(
                            "mma.sync.aligned.m16n8k16.row.col.f32.f16.f16.f32 "
                            "{%0,%1,%2,%3}, {%4,%5,%6,%7}, {%8,%9}, {%0,%1,%2,%3};"
                            : "+f"(acc[mt][nt * 2 + nf][0]), "+f"(acc[mt][nt * 2 + nf][1]),
                              "+f"(acc[mt][nt * 2 + nf][2]), "+f"(acc[mt][nt * 2 + nf][3])
                            : "r"(bufA[cb][mt][0]), "r"(bufA[cb][mt][1]),
                              "r"(bufA[cb][mt][2]), "r"(bufA[cb][mt][3]),
                              "r"(bufB[cb][nt][nf]), "r"(bufB[cb][nt][2 + nf]));
        }
        sbuf++;
        if (sbuf == STG) sbuf = 0;
    }

    // epilogue
    int mbase = bm + wm * 32 + (lane >> 2);
    int nbase = bn + wn * 32 + (lane & 3) * 2;
    #pragma unroll
    for (int mt = 0; mt < 2; mt++) {
        #pragma unroll
        for (int jf = 0; jf < 4; jf++) {
            int col = nbase + (jf >> 1) * 16 + (jf & 1) * 8;
            int m0 = mbase + mt * 16;
            float b0, b1;
            if (EPI == 1 && col >= 512) {
                if (col < 528)      { b0 = bB[col - 512]; b1 = bB[col - 511]; }
                else if (col < 544) { b0 = bC[col - 528]; b1 = bC[col - 527]; }
                else                { b0 = 0.f; b1 = 0.f; }
            } else {
                b0 = bias[col]; b1 = bias[col + 1];
            }
            float v0 = acc[mt][jf][0] + b0, v1 = acc[mt][jf][1] + b1;
            float v2 = acc[mt][jf][2] + b0, v3 = acc[mt][jf][3] + b1;

            if (EPI == 1 && col >= 512) {
                if (col < 528) {
                    int n = col - 512;
                    *(float2*)(g_Bm + (size_t)m0 * NN + n)       = make_float2(v0, v1);
                    *(float2*)(g_Bm + (size_t)(m0 + 8) * NN + n) = make_float2(v2, v3);
                } else if (col < 544) {
                    int n = col - 528;
                    *(float2*)(g_Cm + (size_t)m0 * NN + n)       = make_float2(v0, v1);
                    *(float2*)(g_Cm + (size_t)(m0 + 8) * NN + n) = make_float2(v2, v3);
                }
                continue;
            }
            if (EPI == 1) { v0 = softplusf(v0); v1 = softplusf(v1); v2 = softplusf(v2); v3 = softplusf(v3); }
            *(float2*)(C + (size_t)m0 * DD + col)       = make_float2(v0, v1);
            *(float2*)(C + (size_t)(m0 + 8) * DD + col) = make_float2(v2, v3);
            if (EPI == 2) {
                __half h0 = __float2half_rn(v0), h1 = __float2half_rn(v1);
                __half h2 = __float2half_rn(v2), h3 = __float2half_rn(v3);
                __half2 hv0(h0, h1), hv1(h2, h3);
                __half2 lv0(__float2half_rn(v0 - __half2float(h0)),
                            __float2half_rn(v1 - __half2float(h1)));
                __half2 lv1(__float2half_rn(v2 - __half2float(h2)),
                            __float2half_rn(v3 - __half2float(h3)));
                __half* r0 = xout + (size_t)m0 * KC + col;
                __half* r1 = xout + (size_t)(m0 + 8) * KC + col;
                *(__half2*)(r0)        = hv0;
                *(__half2*)(r0 + 512)  = lv0;
                *(__half2*)(r1)        = hv1;
                *(__half2*)(r1 + 512)  = lv1;
            }
        }
    }
}

// ---------------------------------------------------------------------------
// Merged prep kernel. grid (16, 16, 8), block 256.
// z=0..3: transpose+split Wdt0/Wdt1/Wlin0/Wdec -> slots 0/1/2/4
// z=4:    WB/WC split into rows 512..575 of slots 0,1 (blocks with by<2)
// z=5:    row-split Wlin2 -> g_Xcat1[0..511]  (temp A for gemmF)
// z=6:    beff = bdec + blin2 @ Wdec          (blocks with id<64)
// z=7:    split x -> g_Xcat0 (8 chunks per block)
// ---------------------------------------------------------------------------
__global__ void prep_k(const float* __restrict__ Wdt, const float* __restrict__ Wlin,
                       const float* __restrict__ Wdec, const float* __restrict__ WB,
                       const float* __restrict__ WC, const float* __restrict__ blin,
                       const float* __restrict__ bdec, const float4* __restrict__ x)
{
    __shared__ float t[32][33];
    __shared__ float part[32][8];
    int z = blockIdx.z;
    int bx = blockIdx.x, by = blockIdx.y;
    int tid = threadIdx.x;
    int tx = tid & 31, ty = tid >> 5;
    int bid = by * 16 + bx;

    if (z < 4) {
        const float* W = (z == 0) ? Wdt
                       : (z == 1) ? Wdt + (size_t)DD * DD
                       : (z == 2) ? Wlin
                                  : Wdec;
        int slot = (z == 3) ? 4 : z;
        __half* out = g_Wcat + (size_t)slot * NW * KC;
        int bk = bx * 32, bn = by * 32;
        #pragma unroll
        for (int i = 0; i < 32; i += 8)
            t[ty + i][tx] = W[(size_t)(bk + ty + i) * DD + bn + tx];
        __syncthreads();
        #pragma unroll
        for (int i = 0; i < 32; i += 8) {
            float v = t[tx][ty + i];
            __half h = __float2half_rn(v);
            size_t o = (size_t)(bn + ty + i) * KC + bk + tx;
            out[o]       = h;
            out[o + 512] = h;
        }
    } else if (z == 4) {
        if (by >= 2) return;
        int l = by;
        int bk = bx * 32;
        __half* out = g_Wcat + (size_t)l * NW * KC + (size_t)512 * KC;
        for (int r = ty; r < 64; r += 8) {
            float v = 0.f;
            if (r < 16)      v = WB[(size_t)l * DD * NN + (size_t)(bk + tx) * NN + r];
            else if (r < 32) v = WC[(size_t)l * DD * NN + (size_t)(bk + tx) * NN + (r - 16)];
            __half h = __float2half_rn(v);
            size_t o = (size_t)r * KC + bk + tx;
            out[o]       = h;
            out[o + 512] = h;
        }
    } else if (z == 5) {
        // row-split Wlin2 (512x512 float) -> g_Xcat1 as [hi|lo], KC stride
        const float4* in = (const float4*)(Wlin + (size_t)DD * DD);
        int i = bid * 256 + tid;           // 65536 float4 total
        int m = i >> 7;
        int k4 = (i & 127) << 2;
        float4 v = in[i];
        __half2 h0(__float2half_rn(v.x), __float2half_rn(v.y));
        __half2 h1(__float2half_rn(v.z), __float2half_rn(v.w));
        __half2 l0(__float2half_rn(v.x - __half2float(h0.x)),
                   __float2half_rn(v.y - __half2float(h0.y)));
        __half2 l1(__float2half_rn(v.z - __half2float(h1.x)),
                   __float2half_rn(v.w - __half2float(h1.y)));
        __half* row = g_Xcat1 + (size_t)m * KC;
        *(__half2*)(row + k4)       = h0;
        *(__half2*)(row + k4 + 2)   = h1;
        *(__half2*)(row + k4 + 512) = l0;
        *(__half2*)(row + k4 + 514) = l1;
    } else if (z == 6) {
        if (bid >= 64) return;
        const float* blin2 = blin + DD;
        int og = tid & 7;
        int r  = tid >> 3;                 // 0..31
        int o  = bid * 8 + og;
        float acc = 0.f;
        int d0 = r * 16;
        #pragma unroll
        for (int d = d0; d < d0 + 16; d++)
            acc = fmaf(blin2[d], Wdec[(size_t)d * DD + o], acc);
        part[r][og] = acc;
        __syncthreads();
        if (tid < 8) {
            float s = bdec[bid * 8 + tid];
            #pragma unroll
            for (int i = 0; i < 32; i++) s += part[i][tid];
            g_beff[bid * 8 + tid] = s;
        }
    } else {
        // z == 7: split x (BLD/4 = 524288 float4) -> g_Xcat0, 8 chunks/block
        #pragma unroll
        for (int it = 0; it < 8; it++) {
            int i = (bid * 8 + it) * 256 + tid;
            int m = i >> 7;
            int k4 = (i & 127) << 2;
            float4 v = x[i];
            __half2 h0(__float2half_rn(v.x), __float2half_rn(v.y));
            __half2 h1(__float2half_rn(v.z), __float2half_rn(v.w));
            __half2 l0(__float2half_rn(v.x - __half2float(h0.x)),
                       __float2half_rn(v.y - __half2float(h0.y)));
            __half2 l1(__float2half_rn(v.z - __half2float(h1.x)),
                       __float2half_rn(v.w - __half2float(h1.y)));
            __half* row = g_Xcat0 + (size_t)m * KC;
            *(__half2*)(row + k4)       = h0;
            *(__half2*)(row + k4 + 2)   = h1;
            *(__half2*)(row + k4 + 512) = l0;
            *(__half2*)(row + k4 + 514) = l1;
        }
    }
}

// Single-slot transpose+split (fused decoder weight F from g_y -> slot 4).
__global__ void tsplit_one_k(const float* __restrict__ W, __half* __restrict__ out)
{
    __shared__ float t[32][33];
    int bk = blockIdx.x * 32, bn = blockIdx.y * 32;
    int tx = threadIdx.x, ty = threadIdx.y;
    #pragma unroll
    for (int i = 0; i < 32; i += 8)
        t[ty + i][tx] = W[(size_t)(bk + ty + i) * DD + bn + tx];
    __syncthreads();
    #pragma unroll
    for (int i = 0; i < 32; i += 8) {
        float v = t[tx][ty + i];
        __half h = __float2half_rn(v);
        size_t o = (size_t)(bn + ty + i) * KC + bk + tx;
        out[o]       = h;
        out[o + 512] = h;
    }
}

// ---------------------------------------------------------------------------
// Scan pass 1: local chunk scan from zero; store P, He.
// grid = (4, NCH, 4), block 128
// ---------------------------------------------------------------------------
__global__ void scan1_k(const float* __restrict__ yin, const float* __restrict__ A)
{
    __shared__ float sB[LCH * NN];
    int d = blockIdx.x * 128 + threadIdx.x;
    int c = blockIdx.y, b = blockIdx.z;
    int t0 = c * LCH;

    const float4* src = (const float4*)(g_Bm + ((size_t)b * LL + t0) * NN);
    #pragma unroll
    for (int i = threadIdx.x; i < LCH * NN / 4; i += 128)
        ((float4*)sB)[i] = src[i];
    __syncthreads();

    float av[NN], h[NN], p[NN];
    #pragma unroll
    for (int q = 0; q < 4; q++)
        *(float4*)(av + q * 4) = *(const float4*)(A + (size_t)d * NN + q * 4);
    #pragma unroll
    for (int n = 0; n < NN; n++) { h[n] = 0.f; p[n] = 1.f; }

    const float* dtp = g_dt + ((size_t)b * LL + t0) * DD + d;
    const float* yp  = yin  + ((size_t)b * LL + t0) * DD + d;

    for (int t = 0; t < LCH; t++) {
        float dv = dtp[(size_t)t * DD];
        float u  = dv * yp[(size_t)t * DD];
        #pragma unroll
        for (int n = 0; n < NN; n++) {
            float e = __expf(dv * av[n]);
            p[n] *= e;
            h[n] = fmaf(e, h[n], u * sB[t * NN + n]);
        }
    }

    size_t o = (((size_t)b * NCH + c) * DD + d) * NN;
    #pragma unroll
    for (int q = 0; q < 4; q++) {
        *(float4*)(g_P  + o + q * 4) = *(float4*)(p + q * 4);
        *(float4*)(g_He + o + q * 4) = *(float4*)(h + q * 4);
    }
}

// ---------------------------------------------------------------------------
// Scan pass 2 (batched loads across NCH chunks)
// ---------------------------------------------------------------------------
__global__ void scan2_k()
{
    int tid = blockIdx.x * blockDim.x + threadIdx.x;
    int b  = tid >> 13;
    int dn = tid & 8191;
    size_t base = (size_t)b * NCH * DD * NN + dn;

    float p[NCH], he[NCH];
    #pragma unroll
    for (int c = 0; c < NCH; c++) {
        p[c]  = g_P [base + (size_t)c * DD * NN];
        he[c] = g_He[base + (size_t)c * DD * NN];
    }
    float hc = 0.f;
    float cr[NCH];
    #pragma unroll
    for (int c = 0; c < NCH; c++) {
        cr[c] = hc;
        hc = fmaf(p[c], hc, he[c]);
    }
    #pragma unroll
    for (int c = 0; c < NCH; c++)
        g_carry[base + (size_t)c * DD * NN] = cr[c];
}

// ---------------------------------------------------------------------------
// Scan pass 3: rescan with carry; write z as fp16 split into Xcat1.
// grid = (4, NCH, 4), block 128
// ---------------------------------------------------------------------------
__global__ void scan3_k(const float* __restrict__ yin, const float* __restrict__ A,
                        const float* __restrict__ Dskip)
{
    __shared__ float sB[LCH * NN];
    __shared__ float sC[LCH * NN];
    int d = blockIdx.x * 128 + threadIdx.x;
    int c = blockIdx.y, b = blockIdx.z;
    int t0 = c * LCH;

    {
        const float4* srcB = (const float4*)(g_Bm + ((size_t)b * LL + t0) * NN);
        const float4* srcC = (const float4*)(g_Cm + ((size_t)b * LL + t0) * NN);
        #pragma unroll
        for (int i = threadIdx.x; i < LCH * NN / 4; i += 128) {
            ((float4*)sB)[i] = srcB[i];
            ((float4*)sC)[i] = srcC[i];
        }
    }
    __syncthreads();

    float av[NN], h[NN];
    #pragma unroll
    for (int q = 0; q < 4; q++)
        *(float4*)(av + q * 4) = *(const float4*)(A + (size_t)d * NN + q * 4);
    size_t co = (((size_t)b * NCH + c) * DD + d) * NN;
    #pragma unroll
    for (int q = 0; q < 4; q++)
        *(float4*)(h + q * 4) = *(const float4*)(g_carry + co + q * 4);

    float ds = Dskip[d];
    const float* dtp = g_dt + ((size_t)b * LL + t0) * DD + d;
    const float* yp  = yin  + ((size_t)b * LL + t0) * DD + d;
    __half* zb = g_Xcat1 + ((size_t)b * LL + t0) * KC + d;

    for (int t = 0; t < LCH; t++) {
        float dv = dtp[(size_t)t * DD];
        float yv = yp[(size_t)t * DD];
        float u  = dv * yv;
        float acc = 0.f;
        #pragma unroll
        for (int n = 0; n < NN; n++) {
            float e = __expf(dv * av[n]);
            h[n] = fmaf(e, h[n], u * sB[t * NN + n]);
            acc = fmaf(h[n], sC[t * NN + n], acc);
        }
        float z = fmaxf(fmaf(ds, yv, acc), 0.f);
        __half hi = __float2half_rn(z);
        __half lo = __float2half_rn(z - __half2float(hi));
        __half* zr = zb + (size_t)t * KC;
        zr[0]   = hi;
        zr[512] = lo;
    }
}

// ---------------------------------------------------------------------------
// Host launcher
// ---------------------------------------------------------------------------
extern "C" void kernel_launch(void* const* d_in, const int* in_sizes, int n_in,
                              void* d_out, int out_size)
{
    const float* x     = (const float*)d_in[0];
    const float* A     = (const float*)d_in[1];
    const float* Dskip = (const float*)d_in[2];
    const float* WB    = (const float*)d_in[3];
    const float* bB    = (const float*)d_in[4];
    const float* WC    = (const float*)d_in[5];
    const float* bC    = (const float*)d_in[6];
    const float* Wdt   = (const float*)d_in[7];
    const float* bdt   = (const float*)d_in[8];
    const float* Wlin  = (const float*)d_in[9];
    const float* blin  = (const float*)d_in[10];
    const float* Wdec  = (const float*)d_in[11];
    const float* bdec  = (const float*)d_in[12];
    float* out = (float*)d_out;

    float *py, *pdt, *pbeff, *pbzero;
    __half *px0, *px1, *pwc;
    cudaGetSymbolAddress((void**)&py,     g_y);
    cudaGetSymbolAddress((void**)&pdt,    g_dt);
    cudaGetSymbolAddress((void**)&pbeff,  g_beff);
    cudaGetSymbolAddress((void**)&pbzero, g_bzero);
    cudaGetSymbolAddress((void**)&px0,    g_Xcat0);
    cudaGetSymbolAddress((void**)&px1,    g_Xcat1);
    cudaGetSymbolAddress((void**)&pwc,    g_Wcat);

    cudaFuncSetAttribute(tc_gemm<0>, cudaFuncAttributeMaxDynamicSharedMemorySize, TC_SMEM);
    cudaFuncSetAttribute(tc_gemm<1>, cudaFuncAttributeMaxDynamicSharedMemorySize, TC_SMEM);
    cudaFuncSetAttribute(tc_gemm<2>, cudaFuncAttributeMaxDynamicSharedMemorySize, TC_SMEM);

    const size_t WCSZ = (size_t)NW * KC;

    // --- Prep (1 launch): weight splits, BC split, Wlin2 split (->Xcat1),
    //     beff, x split (->Xcat0) ---
    prep_k<<<dim3(16, 16, 8), 256>>>(Wdt, Wlin, Wdec, WB, WC, blin, bdec, (const float4*)x);

    // --- Fused decoder weight: F = Wlin2 @ Wdec -> g_y, then split to slot 4 ---
    tc_gemm<0><<<dim3(8, 4), 256, TC_SMEM>>>(px1, pwc + 4 * WCSZ, pbzero,
                                             nullptr, nullptr, py, nullptr);
    tsplit_one_k<<<dim3(16, 16), dim3(32, 8)>>>(py, pwc + 4 * WCSZ);

    // --- Main pipeline ---
    dim3 gG1(NW / 64, MM / 128);   // (9, 32) fused dt+BC
    dim3 gG(DD / 64, MM / 128);    // (8, 32)
    dim3 gs(DD / 128, NCH, BB);

    // Layer 0
    tc_gemm<1><<<gG1, 256, TC_SMEM>>>(px0, pwc + 0 * WCSZ, bdt,
                                      bB, bC, pdt, nullptr);
    scan1_k<<<gs, 128>>>(x, A);
    scan2_k<<<(BB * DD * NN) / 256, 256>>>();
    scan3_k<<<gs, 128>>>(x, A, Dskip);
    tc_gemm<2><<<gG, 256, TC_SMEM>>>(px1, pwc + 2 * WCSZ, blin,
                                     nullptr, nullptr, py, px0);

    // Layer 1
    tc_gemm<1><<<gG1, 256, TC_SMEM>>>(px0, pwc + 1 * WCSZ, bdt + DD,
                                      bB + NN, bC + NN, pdt, nullptr);
    scan1_k<<<gs, 128>>>(py, A + (size_t)DD * NN);
    scan2_k<<<(BB * DD * NN) / 256, 256>>>();
    scan3_k<<<gs, 128>>>(py, A + (size_t)DD * NN, Dskip + DD);

    // Fused lin2+dec: out = z2 @ F + beff
    tc_gemm<0><<<gG, 256, TC_SMEM>>>(px1, pwc + 4 * WCSZ, pbeff,
                                     nullptr, nullptr, out, nullptr);
}

// round 15
// speedup vs baseline: 1.6431x; 1.0123x over previous
#include <cuda_runtime.h>
#include <cuda_fp16.h>
#include <math.h>
#include <cstdint>

// Problem constants
#define BB 4
#define LL 1024
#define DD 512
#define NN 16
#define OUTD 512
#define NLAYER 2
#define NCH 32
#define LCH 32

#define BLD (BB*LL*DD)
#define BLN (BB*LL*NN)
#define CHN (BB*NCH*DD*NN)

#define MM (BB*LL)      // 4096 rows
#define KC 1024         // concatenated K (2x512): [Xh|Xl] x [Wh|Wh]
#define NW 576          // widened N for fused dt+B+C gemm
#define NSCANBLK 512    // fused scan grid size (4*NCH*BB)

// Scratch
__device__ float g_y[BLD];
__device__ float g_dt[BLD];
__device__ float g_Bm[BLN];
__device__ float g_Cm[BLN];
__device__ float g_P[CHN];
__device__ float g_He[CHN];
__device__ float g_carry[CHN];
__device__ float g_beff[DD];
__device__ float g_bzero[DD];
__device__ volatile unsigned g_barc[4];           // grid-barrier counters
__device__ __half g_Xcat0[(size_t)MM * KC];       // [Xh | Xl]
__device__ __half g_Xcat1[(size_t)MM * KC];       // z split (also temp Wlin2 split)
__device__ __half g_Wcat[5 * (size_t)NW * KC];    // slots: 0,1=Wdt; 2=Wlin0; 3=Wdec; 4=F

__device__ __forceinline__ float softplusf(float x) {
    return fmaxf(x, 0.f) + log1pf(__expf(-fabsf(x)));
}

__device__ __forceinline__ uint32_t smem_u32(const void* p) {
    uint32_t a;
    asm("{ .reg .u64 t; cvta.to.shared.u64 t, %1; cvt.u32.u64 %0, t; }" : "=r"(a) : "l"(p));
    return a;
}

// swizzled byte offset inside a 128B-row tile
__device__ __forceinline__ uint32_t swz(int r, int c) {
    return ((uint32_t)r << 7) + ((uint32_t)(c ^ (r & 7)) << 4);
}

// grid barrier (all NSCANBLK blocks co-resident by construction)
__device__ __forceinline__ void gridbar(int i) {
    __threadfence();
    __syncthreads();
    if (threadIdx.x == 0) {
        atomicAdd((unsigned*)&g_barc[i], 1u);
        while (g_barc[i] < NSCANBLK) {}
    }
    __syncthreads();
    __threadfence();
}

#define BK 64
#define STG 3
#define ABYTES 16384
#define BBYTES 8192
#define STAGE_BYTES (ABYTES + BBYTES)
#define TC_SMEM (STG * STAGE_BYTES)

// ---------------------------------------------------------------------------
// GEMM mainloop macro body shared by tc_gemm and the combo kernel.
// Produces acc[2][4][4] for tile (bm, bn) from (Aop, Bop).
// ---------------------------------------------------------------------------
#define GEMM_MAINLOOP(Aop, Bop)                                                              \
    extern __shared__ char smem[];                                                          \
    uint32_t sbase = smem_u32(smem);                                                        \
    int tid = threadIdx.x, wid = tid >> 5, lane = tid & 31;                                 \
    int wm = wid & 3, wn = wid >> 2;                                                        \
    int lrow = ((lane >> 3) & 1) * 8 + (lane & 7);                                          \
    int lck = lane >> 4;                                                                    \
    uint32_t aoff[2][4], boff[2][4];                                                        \
    _Pragma("unroll")                                                                       \
    for (int mt = 0; mt < 2; mt++)                                                          \
        _Pragma("unroll")                                                                   \
        for (int ks = 0; ks < 4; ks++)                                                      \
            aoff[mt][ks] = swz(wm * 32 + mt * 16 + lrow, ks * 2 + lck);                     \
    _Pragma("unroll")                                                                       \
    for (int nt = 0; nt < 2; nt++)                                                          \
        _Pragma("unroll")                                                                   \
        for (int ks = 0; ks < 4; ks++)                                                      \
            boff[nt][ks] = ABYTES + swz(wn * 32 + nt * 16 + lrow, ks * 2 + lck);            \
    int ra = tid >> 1, ca0 = (tid & 1) * 4;                                                 \
    int rb = tid >> 2, cb0 = (tid & 3) * 2;                                                 \
    const __half* gA = (Aop) + (size_t)(bm + ra) * KC + ca0 * 8;                            \
    const __half* gB = (Bop) + (size_t)(bn + rb) * KC + cb0 * 8;                            \
    uint32_t dA[4], dB[2];                                                                  \
    _Pragma("unroll")                                                                       \
    for (int i = 0; i < 4; i++) dA[i] = swz(ra, ca0 + i);                                   \
    _Pragma("unroll")                                                                       \
    for (int i = 0; i < 2; i++) dB[i] = ABYTES + swz(rb, cb0 + i);                          \
    float acc[2][4][4];                                                                     \
    _Pragma("unroll")                                                                       \
    for (int i = 0; i < 2; i++)                                                             \
        _Pragma("unroll")                                                                   \
        for (int j = 0; j < 4; j++)                                                         \
            _Pragma("unroll")                                                               \
            for (int q = 0; q < 4; q++) acc[i][j][q] = 0.f;                                 \
    const int NKB = KC / BK;                                                                \
    _Pragma("unroll")                                                                       \
    for (int s = 0; s < STG - 1; s++) {                                                     \
        uint32_t st = sbase + s * STAGE_BYTES;                                              \
        int ko = s * BK;                                                                    \
        _Pragma("unroll")                                                                   \
        for (int i = 0; i < 4; i++)                                                         \
            asm volatile("cp.async.cg.shared.global [%0], [%1], 16;"                        \
                         :: "r"(st + dA[i]), "l"(gA + ko + i * 8));                         \
        _Pragma("unroll")                                                                   \
        for (int i = 0; i < 2; i++)                                                         \
            asm volatile("cp.async.cg.shared.global [%0], [%1], 16;"                        \
                         :: "r"(st + dB[i]), "l"(gB + ko + i * 8));                         \
        asm volatile("cp.async.commit_group;" ::: "memory");                                \
    }                                                                                       \
    uint32_t bufA[2][2][4], bufB[2][2][4];                                                  \
    int sbuf = 0;                                                                           \
    for (int kb = 0; kb < NKB; kb++) {                                                      \
        asm volatile("cp.async.wait_group %0;" :: "n"(STG - 2) : "memory");                 \
        __syncthreads();                                                                    \
        int knext = kb + STG - 1;                                                           \
        if (knext < NKB) {                                                                  \
            int sn = knext % STG;                                                           \
            uint32_t st = sbase + sn * STAGE_BYTES;                                         \
            int ko = knext * BK;                                                            \
            _Pragma("unroll")                                                               \
            for (int i = 0; i < 4; i++)                                                     \
                asm volatile("cp.async.cg.shared.global [%0], [%1], 16;"                    \
                             :: "r"(st + dA[i]), "l"(gA + ko + i * 8));                     \
            _Pragma("unroll")                                                               \
            for (int i = 0; i < 2; i++)                                                     \
                asm volatile("cp.async.cg.shared.global [%0], [%1], 16;"                    \
                             :: "r"(st + dB[i]), "l"(gB + ko + i * 8));                     \
        }                                                                                   \
        asm volatile("cp.async.commit_group;" ::: "memory");                                \
        uint32_t st = sbase + sbuf * STAGE_BYTES;                                           \
        _Pragma("unroll")                                                                   \
        for (int mt = 0; mt < 2; mt++)                                                      \
            asm volatile("ldmatrix.sync.aligned.m8n8.x4.shared.b16 {%0,%1,%2,%3}, [%4];"    \
                         : "=r"(bufA[0][mt][0]), "=r"(bufA[0][mt][1]),                      \
                           "=r"(bufA[0][mt][2]), "=r"(bufA[0][mt][3])                       \
                         : "r"(st + aoff[mt][0]));                                          \
        _Pragma("unroll")                                                                   \
        for (int nt = 0; nt < 2; nt++)                                                      \
            asm volatile("ldmatrix.sync.aligned.m8n8.x4.shared.b16 {%0,%1,%2,%3}, [%4];"    \
                         : "=r"(bufB[0][nt][0]), "=r"(bufB[0][nt][1]),                      \
                           "=r"(bufB[0][nt][2]), "=r"(bufB[0][nt][3])                       \
                         : "r"(st + boff[nt][0]));                                          \
        _Pragma("unroll")                                                                   \
        for (int ks = 0; ks < 4; ks++) {                                                    \
            int cb = ks & 1, nb = cb ^ 1;                                                   \
            if (ks < 3) {                                                                   \
                _Pragma("unroll")                                                           \
                for (int mt = 0; mt < 2; mt++)                                              \
                    asm volatile("ldmatrix.sync.aligned.m8n8.x4.shared.b16 {%0,%1,%2,%3}, [%4];" \
                                 : "=r"(bufA[nb][mt][0]), "=r"(bufA[nb][mt][1]),            \
                                   "=r"(bufA[nb][mt][2]), "=r"(bufA[nb][mt][3])             \
                                 : "r"(st + aoff[mt][ks + 1]));                             \
                _Pragma("unroll")                                                           \
                for (int nt = 0; nt < 2; nt++)                                              \
                    asm volatile("ldmatrix.sync.aligned.m8n8.x4.shared.b16 {%0,%1,%2,%3}, [%4];" \
                                 : "=r"(bufB[nb][nt][0]), "=r"(bufB[nb][nt][1]),            \
                                   "=r"(bufB[nb][nt][2]), "=r"(bufB[nb][nt][3])             \
                                 : "r"(st + boff[nt][ks + 1]));                             \
            }                                                                               \
            _Pragma("unroll")                                                               \
            for (int mt = 0; mt < 2; mt++)                                                  \
                _Pragma("unroll")                                                           \
                for (int nt = 0; nt < 2; nt++)                                              \
                    _Pragma("unroll")                                                       \
                    for (int nf = 0; nf < 2; nf++)                                          \
                        asm volatile(                                                       \
                            "mma.sync.aligned.m16n8k16.row.col.f32.f16.f16.f32 "            \
                            "{%0,%1,%2,%3}, {%4,%5,%6,%7}, {%8,%9}, {%0,%1,%2,%3};"         \
                            : "+f"(acc[mt][nt * 2 + nf][0]), "+f"(acc[mt][nt * 2 + nf][1]), \
                              "+f"(acc[mt][nt * 2 + nf][2]), "+f"(acc[mt][nt * 2 + nf][3])  \
                            : "r"(bufA[cb][mt][0]), "r"(bufA[cb][mt][1]),                   \
                              "r"(bufA[cb][mt][2]), "r"(bufA[cb][mt][3]),                   \
                              "r"(bufB[cb][nt][nf]), "r"(bufB[cb][nt][2 + nf]));            \
        }                                                                                   \
        sbuf++;                                                                             \
        if (sbuf == STG) sbuf = 0;                                                          \
    }

// ---------------------------------------------------------------------------
// tc_gemm: EPI 0 = bias; EPI 2 = bias + fp16-split to xout. (EPI 1 lives in combo
// and a standalone variant below.)
// ---------------------------------------------------------------------------
template<int EPI>
__global__ void __launch_bounds__(256, 3)
tc_gemm(const __half* __restrict__ Ain, const __half* __restrict__ Bw,
        const float* __restrict__ bias, const float* __restrict__ bB,
        const float* __restrict__ bC, float* __restrict__ C,
        __half* __restrict__ xout)
{
    int bn = blockIdx.x * 64, bm = blockIdx.y * 128;
    GEMM_MAINLOOP(Ain, Bw)

    int mbase = bm + wm * 32 + (lane >> 2);
    int nbase = bn + wn * 32 + (lane & 3) * 2;
    #pragma unroll
    for (int mt = 0; mt < 2; mt++) {
        #pragma unroll
        for (int jf = 0; jf < 4; jf++) {
            int col = nbase + (jf >> 1) * 16 + (jf & 1) * 8;
            int m0 = mbase + mt * 16;
            float b0, b1;
            if (EPI == 1 && col >= 512) {
                if (col < 528)      { b0 = bB[col - 512]; b1 = bB[col - 511]; }
                else if (col < 544) { b0 = bC[col - 528]; b1 = bC[col - 527]; }
                else                { b0 = 0.f; b1 = 0.f; }
            } else {
                b0 = bias[col]; b1 = bias[col + 1];
            }
            float v0 = acc[mt][jf][0] + b0, v1 = acc[mt][jf][1] + b1;
            float v2 = acc[mt][jf][2] + b0, v3 = acc[mt][jf][3] + b1;

            if (EPI == 1 && col >= 512) {
                if (col < 528) {
                    int n = col - 512;
                    *(float2*)(g_Bm + (size_t)m0 * NN + n)       = make_float2(v0, v1);
                    *(float2*)(g_Bm + (size_t)(m0 + 8) * NN + n) = make_float2(v2, v3);
                } else if (col < 544) {
                    int n = col - 528;
                    *(float2*)(g_Cm + (size_t)m0 * NN + n)       = make_float2(v0, v1);
                    *(float2*)(g_Cm + (size_t)(m0 + 8) * NN + n) = make_float2(v2, v3);
                }
                continue;
            }
            if (EPI == 1) { v0 = softplusf(v0); v1 = softplusf(v1); v2 = softplusf(v2); v3 = softplusf(v3); }
            *(float2*)(C + (size_t)m0 * DD + col)       = make_float2(v0, v1);
            *(float2*)(C + (size_t)(m0 + 8) * DD + col) = make_float2(v2, v3);
            if (EPI == 2) {
                __half h0 = __float2half_rn(v0), h1 = __float2half_rn(v1);
                __half h2 = __float2half_rn(v2), h3 = __float2half_rn(v3);
                __half2 hv0(h0, h1), hv1(h2, h3);
                __half2 lv0(__float2half_rn(v0 - __half2float(h0)),
                            __float2half_rn(v1 - __half2float(h1)));
                __half2 lv1(__float2half_rn(v2 - __half2float(h2)),
                            __float2half_rn(v3 - __half2float(h3)));
                __half* r0 = xout + (size_t)m0 * KC + col;
                __half* r1 = xout + (size_t)(m0 + 8) * KC + col;
                *(__half2*)(r0)        = hv0;
                *(__half2*)(r0 + 512)  = lv0;
                *(__half2*)(r1)        = hv1;
                *(__half2*)(r1 + 512)  = lv1;
            }
        }
    }
}

// Explicit instantiation of EPI=1 via template (used standalone for layer 1)
template __global__ void tc_gemm<0>(const __half*, const __half*, const float*,
                                    const float*, const float*, float*, __half*);
template __global__ void tc_gemm<1>(const __half*, const __half*, const float*,
                                    const float*, const float*, float*, __half*);
template __global__ void tc_gemm<2>(const __half*, const __half*, const float*,
                                    const float*, const float*, float*, __half*);

// ---------------------------------------------------------------------------
// Combo kernel: grid (9, 36).
//   by <  32: layer-0 dt GEMM (EPI1): A=g_Xcat0, B=slot0, C=g_dt, Bm/Cm fused.
//   by >= 32: F = Wlin2 @ Wdec (A=g_Xcat1 rows 0..511, B=slot3), epilogue writes
//             transposed fp16 split directly into slot 4 (EPI3). bx<8 only.
// ---------------------------------------------------------------------------
__global__ void __launch_bounds__(256, 3)
tc_gemm_combo(const float* __restrict__ bdt0, const float* __restrict__ bB0,
              const float* __restrict__ bC0)
{
    bool fm = (blockIdx.y >= 32);
    if (fm && blockIdx.x >= 8) return;
    int bn = blockIdx.x * 64;
    int bm = fm ? (int)(blockIdx.y - 32) * 128 : (int)blockIdx.y * 128;
    const __half* Aop = fm ? g_Xcat1 : g_Xcat0;
    const __half* Bop = g_Wcat + (size_t)(fm ? 3 : 0) * NW * KC;

    GEMM_MAINLOOP(Aop, Bop)

    int mbase = bm + wm * 32 + (lane >> 2);
    int nbase = bn + wn * 32 + (lane & 3) * 2;
    __half* slot4 = g_Wcat + (size_t)4 * NW * KC;

    #pragma unroll
    for (int mt = 0; mt < 2; mt++) {
        #pragma unroll
        for (int jf = 0; jf < 4; jf++) {
            int col = nbase + (jf >> 1) * 16 + (jf & 1) * 8;
            int m0 = mbase + mt * 16;
            if (fm) {
                // EPI3: F[m][col] -> slot4[col][m] as [hi|hi]
                #pragma unroll
                for (int q = 0; q < 4; q++) {
                    int mm = m0 + (q >> 1) * 8;
                    int cc = col + (q & 1);
                    __half h = __float2half_rn(acc[mt][jf][q]);
                    slot4[(size_t)cc * KC + mm]       = h;
                    slot4[(size_t)cc * KC + mm + 512] = h;
                }
                continue;
            }
            float b0, b1;
            if (col >= 512) {
                if (col < 528)      { b0 = bB0[col - 512]; b1 = bB0[col - 511]; }
                else if (col < 544) { b0 = bC0[col - 528]; b1 = bC0[col - 527]; }
                else                { b0 = 0.f; b1 = 0.f; }
            } else {
                b0 = bdt0[col]; b1 = bdt0[col + 1];
            }
            float v0 = acc[mt][jf][0] + b0, v1 = acc[mt][jf][1] + b1;
            float v2 = acc[mt][jf][2] + b0, v3 = acc[mt][jf][3] + b1;
            if (col >= 512) {
                if (col < 528) {
                    int n = col - 512;
                    *(float2*)(g_Bm + (size_t)m0 * NN + n)       = make_float2(v0, v1);
                    *(float2*)(g_Bm + (size_t)(m0 + 8) * NN + n) = make_float2(v2, v3);
                } else if (col < 544) {
                    int n = col - 528;
                    *(float2*)(g_Cm + (size_t)m0 * NN + n)       = make_float2(v0, v1);
                    *(float2*)(g_Cm + (size_t)(m0 + 8) * NN + n) = make_float2(v2, v3);
                }
                continue;
            }
            v0 = softplusf(v0); v1 = softplusf(v1); v2 = softplusf(v2); v3 = softplusf(v3);
            *(float2*)(g_dt + (size_t)m0 * DD + col)       = make_float2(v0, v1);
            *(float2*)(g_dt + (size_t)(m0 + 8) * DD + col) = make_float2(v2, v3);
        }
    }
}

// ---------------------------------------------------------------------------
// Merged prep kernel. grid (16, 16, 8), block 256.
// z=0..3: transpose+split Wdt0/Wdt1/Wlin0/Wdec -> slots 0/1/2/3
// z=4: WB/WC split -> rows 512..575 of slots 0,1 ; z=5: Wlin2 row-split -> Xcat1
// z=6: beff + barrier-counter reset ; z=7: split x -> Xcat0
// ---------------------------------------------------------------------------
__global__ void prep_k(const float* __restrict__ Wdt, const float* __restrict__ Wlin,
                       const float* __restrict__ Wdec, const float* __restrict__ WB,
                       const float* __restrict__ WC, const float* __restrict__ blin,
                       const float* __restrict__ bdec, const float4* __restrict__ x)
{
    __shared__ float t[32][33];
    __shared__ float part[32][8];
    int z = blockIdx.z;
    int bx = blockIdx.x, by = blockIdx.y;
    int tid = threadIdx.x;
    int tx = tid & 31, ty = tid >> 5;
    int bid = by * 16 + bx;

    if (z < 4) {
        const float* W = (z == 0) ? Wdt
                       : (z == 1) ? Wdt + (size_t)DD * DD
                       : (z == 2) ? Wlin
                                  : Wdec;
        __half* out = g_Wcat + (size_t)z * NW * KC;
        int bk = bx * 32, bn = by * 32;
        #pragma unroll
        for (int i = 0; i < 32; i += 8)
            t[ty + i][tx] = W[(size_t)(bk + ty + i) * DD + bn + tx];
        __syncthreads();
        #pragma unroll
        for (int i = 0; i < 32; i += 8) {
            float v = t[tx][ty + i];
            __half h = __float2half_rn(v);
            size_t o = (size_t)(bn + ty + i) * KC + bk + tx;
            out[o]       = h;
            out[o + 512] = h;
        }
    } else if (z == 4) {
        if (by >= 2) return;
        int l = by;
        int bk = bx * 32;
        __half* out = g_Wcat + (size_t)l * NW * KC + (size_t)512 * KC;
        for (int r = ty; r < 64; r += 8) {
            float v = 0.f;
            if (r < 16)      v = WB[(size_t)l * DD * NN + (size_t)(bk + tx) * NN + r];
            else if (r < 32) v = WC[(size_t)l * DD * NN + (size_t)(bk + tx) * NN + (r - 16)];
            __half h = __float2half_rn(v);
            size_t o = (size_t)r * KC + bk + tx;
            out[o]       = h;
            out[o + 512] = h;
        }
    } else if (z == 5) {
        const float4* in = (const float4*)(Wlin + (size_t)DD * DD);
        int i = bid * 256 + tid;
        int m = i >> 7;
        int k4 = (i & 127) << 2;
        float4 v = in[i];
        __half2 h0(__float2half_rn(v.x), __float2half_rn(v.y));
        __half2 h1(__float2half_rn(v.z), __float2half_rn(v.w));
        __half2 l0(__float2half_rn(v.x - __half2float(h0.x)),
                   __float2half_rn(v.y - __half2float(h0.y)));
        __half2 l1(__float2half_rn(v.z - __half2float(h1.x)),
                   __float2half_rn(v.w - __half2float(h1.y)));
        __half* row = g_Xcat1 + (size_t)m * KC;
        *(__half2*)(row + k4)       = h0;
        *(__half2*)(row + k4 + 2)   = h1;
        *(__half2*)(row + k4 + 512) = l0;
        *(__half2*)(row + k4 + 514) = l1;
    } else if (z == 6) {
        if (bid == 0 && tid < 4) g_barc[tid] = 0;   // barrier reset each replay
        if (bid >= 64) return;
        const float* blin2 = blin + DD;
        int og = tid & 7;
        int r  = tid >> 3;
        int o  = bid * 8 + og;
        float acc = 0.f;
        int d0 = r * 16;
        #pragma unroll
        for (int d = d0; d < d0 + 16; d++)
            acc = fmaf(blin2[d], Wdec[(size_t)d * DD + o], acc);
        part[r][og] = acc;
        __syncthreads();
        if (tid < 8) {
            float s = bdec[bid * 8 + tid];
            #pragma unroll
            for (int i = 0; i < 32; i++) s += part[i][tid];
            g_beff[bid * 8 + tid] = s;
        }
    } else {
        #pragma unroll
        for (int it = 0; it < 8; it++) {
            int i = (bid * 8 + it) * 256 + tid;
            int m = i >> 7;
            int k4 = (i & 127) << 2;
            float4 v = x[i];
            __half2 h0(__float2half_rn(v.x), __float2half_rn(v.y));
            __half2 h1(__float2half_rn(v.z), __float2half_rn(v.w));
            __half2 l0(__float2half_rn(v.x - __half2float(h0.x)),
                       __float2half_rn(v.y - __half2float(h0.y)));
            __half2 l1(__float2half_rn(v.z - __half2float(h1.x)),
                       __float2half_rn(v.w - __half2float(h1.y)));
            __half* row = g_Xcat0 + (size_t)m * KC;
            *(__half2*)(row + k4)       = h0;
            *(__half2*)(row + k4 + 2)   = h1;
            *(__half2*)(row + k4 + 512) = l0;
            *(__half2*)(row + k4 + 514) = l1;
        }
    }
}

// ---------------------------------------------------------------------------
// Fused scan: phase A (local scan -> P,He), grid barrier, phase B (chunk
// combine -> carry), grid barrier, phase C (rescan with carry -> Xcat1 split).
// grid = (4, NCH, BB) = 512 blocks, block 128. barBase selects counters {0,1}
// or {2,3}. All 512 blocks co-resident (4KB smem, ~80 regs -> >=6 blocks/SM).
// ---------------------------------------------------------------------------
__global__ void __launch_bounds__(128)
scan_fused_k(const float* __restrict__ yin, const float* __restrict__ A,
             const float* __restrict__ Dskip, int barBase)
{
    __shared__ float sB[LCH * NN];
    __shared__ float sC[LCH * NN];
    int d = blockIdx.x * 128 + threadIdx.x;
    int c = blockIdx.y, b = blockIdx.z;
    int t0 = c * LCH;
    int fb = blockIdx.x + 4 * (blockIdx.y + NCH * blockIdx.z);

    {
        const float4* srcB = (const float4*)(g_Bm + ((size_t)b * LL + t0) * NN);
        const float4* srcC = (const float4*)(g_Cm + ((size_t)b * LL + t0) * NN);
        #pragma unroll
        for (int i = threadIdx.x; i < LCH * NN / 4; i += 128) {
            ((float4*)sB)[i] = srcB[i];
            ((float4*)sC)[i] = srcC[i];
        }
    }
    __syncthreads();

    float av[NN];
    #pragma unroll
    for (int q = 0; q < 4; q++)
        *(float4*)(av + q * 4) = *(const float4*)(A + (size_t)d * NN + q * 4);

    const float* dtp = g_dt + ((size_t)b * LL + t0) * DD + d;
    const float* yp  = yin  + ((size_t)b * LL + t0) * DD + d;

    // ---- phase A: local scan from zero ----
    {
        float h[NN], p[NN];
        #pragma unroll
        for (int n = 0; n < NN; n++) { h[n] = 0.f; p[n] = 1.f; }
        for (int t = 0; t < LCH; t++) {
            float dv = dtp[(size_t)t * DD];
            float u  = dv * yp[(size_t)t * DD];
            #pragma unroll
            for (int n = 0; n < NN; n++) {
                float e = __expf(dv * av[n]);
                p[n] *= e;
                h[n] = fmaf(e, h[n], u * sB[t * NN + n]);
            }
        }
        size_t o = (((size_t)b * NCH + c) * DD + d) * NN;
        #pragma unroll
        for (int q = 0; q < 4; q++) {
            *(float4*)(g_P  + o + q * 4) = *(float4*)(p + q * 4);
            *(float4*)(g_He + o + q * 4) = *(float4*)(h + q * 4);
        }
    }

    gridbar(barBase);

    // ---- phase B: combine chunks (blocks fb < 256; groups of 8 for reg sanity) ----
    if (fb < 256) {
        int idx = fb * 128 + threadIdx.x;        // 32768 items
        int bb = idx >> 13;
        int dn = idx & 8191;
        size_t base = (size_t)bb * NCH * DD * NN + dn;
        float hc = 0.f;
        for (int g = 0; g < NCH; g += 8) {
            float p[8], he[8];
            #pragma unroll
            for (int j = 0; j < 8; j++) {
                p[j]  = g_P [base + (size_t)(g + j) * DD * NN];
                he[j] = g_He[base + (size_t)(g + j) * DD * NN];
            }
            #pragma unroll
            for (int j = 0; j < 8; j++) {
                g_carry[base + (size_t)(g + j) * DD * NN] = hc;
                hc = fmaf(p[j], hc, he[j]);
            }
        }
    }

    gridbar(barBase + 1);

    // ---- phase C: rescan with carry; emit fp16 split z ----
    {
        float h[NN];
        size_t co = (((size_t)b * NCH + c) * DD + d) * NN;
        #pragma unroll
        for (int q = 0; q < 4; q++)
            *(float4*)(h + q * 4) = *(const float4*)(g_carry + co + q * 4);

        float ds = Dskip[d];
        __half* zb = g_Xcat1 + ((size_t)b * LL + t0) * KC + d;
        for (int t = 0; t < LCH; t++) {
            float dv = dtp[(size_t)t * DD];
            float yv = yp[(size_t)t * DD];
            float u  = dv * yv;
            float acc = 0.f;
            #pragma unroll
            for (int n = 0; n < NN; n++) {
                float e = __expf(dv * av[n]);
                h[n] = fmaf(e, h[n], u * sB[t * NN + n]);
                acc = fmaf(h[n], sC[t * NN + n], acc);
            }
            float z = fmaxf(fmaf(ds, yv, acc), 0.f);
            __half hi = __float2half_rn(z);
            __half lo = __float2half_rn(z - __half2float(hi));
            __half* zr = zb + (size_t)t * KC;
            zr[0]   = hi;
            zr[512] = lo;
        }
    }
}

// ---------------------------------------------------------------------------
// Host launcher (7 graph nodes)
// ---------------------------------------------------------------------------
extern "C" void kernel_launch(void* const* d_in, const int* in_sizes, int n_in,
                              void* d_out, int out_size)
{
    const float* x     = (const float*)d_in[0];
    const float* A     = (const float*)d_in[1];
    const float* Dskip = (const float*)d_in[2];
    const float* WB    = (const float*)d_in[3];
    const float* bB    = (const float*)d_in[4];
    const float* WC    = (const float*)d_in[5];
    const float* bC    = (const float*)d_in[6];
    const float* Wdt   = (const float*)d_in[7];
    const float* bdt   = (const float*)d_in[8];
    const float* Wlin  = (const float*)d_in[9];
    const float* blin  = (const float*)d_in[10];
    const float* Wdec  = (const float*)d_in[11];
    const float* bdec  = (const float*)d_in[12];
    float* out = (float*)d_out;

    float *py, *pdt, *pbeff;
    __half *px0, *px1, *pwc;
    cudaGetSymbolAddress((void**)&py,    g_y);
    cudaGetSymbolAddress((void**)&pdt,   g_dt);
    cudaGetSymbolAddress((void**)&pbeff, g_beff);
    cudaGetSymbolAddress((void**)&px0,   g_Xcat0);
    cudaGetSymbolAddress((void**)&px1,   g_Xcat1);
    cudaGetSymbolAddress((void**)&pwc,   g_Wcat);

    cudaFuncSetAttribute(tc_gemm<0>, cudaFuncAttributeMaxDynamicSharedMemorySize, TC_SMEM);
    cudaFuncSetAttribute(tc_gemm<1>, cudaFuncAttributeMaxDynamicSharedMemorySize, TC_SMEM);
    cudaFuncSetAttribute(tc_gemm<2>, cudaFuncAttributeMaxDynamicSharedMemorySize, TC_SMEM);
    cudaFuncSetAttribute(tc_gemm_combo, cudaFuncAttributeMaxDynamicSharedMemorySize, TC_SMEM);

    const size_t WCSZ = (size_t)NW * KC;

    dim3 gG1(NW / 64, MM / 128);    // (9, 32)
    dim3 gG(DD / 64, MM / 128);     // (8, 32)
    dim3 gsc(DD / 128, NCH, BB);    // (4, 32, 4) = 512 blocks

    // 1) prep: all weight splits, x split, beff, barrier reset
    prep_k<<<dim3(16, 16, 8), 256>>>(Wdt, Wlin, Wdec, WB, WC, blin, bdec, (const float4*)x);

    // 2) layer-0 dt GEMM + fused-F GEMM in one launch
    tc_gemm_combo<<<dim3(9, 36), 256, TC_SMEM>>>(bdt, bB, bC);

    // 3) layer-0 fused scan (barriers 0,1)
    scan_fused_k<<<gsc, 128>>>(x, A, Dskip, 0);

    // 4) layer-0 lin GEMM with fp16-split epilogue -> Xcat0
    tc_gemm<2><<<gG, 256, TC_SMEM>>>(px1, pwc + 2 * WCSZ, blin,
                                     nullptr, nullptr, py, px0);

    // 5) layer-1 dt GEMM (fused Bm/Cm)
    tc_gemm<1><<<gG1, 256, TC_SMEM>>>(px0, pwc + 1 * WCSZ, bdt + DD,
                                      bB + NN, bC + NN, pdt, nullptr);

    // 6) layer-1 fused scan (barriers 2,3)
    scan_fused_k<<<gsc, 128>>>(py, A + (size_t)DD * NN, Dskip + DD, 2);

    // 7) fused lin2+dec: out = z2 @ F + beff
    tc_gemm<0><<<gG, 256, TC_SMEM>>>(px1, pwc + 4 * WCSZ, pbeff,
                                     nullptr, nullptr, out, nullptr);
}

// round 16
// speedup vs baseline: 1.6716x; 1.0174x over previous
#include <cuda_runtime.h>
#include <cuda_fp16.h>
#include <math.h>
#include <cstdint>

// Problem constants
#define BB 4
#define LL 1024
#define DD 512
#define NN 16
#define OUTD 512
#define NLAYER 2
#define NCH 32
#define LCH 32

#define BLD (BB*LL*DD)
#define BLN (BB*LL*NN)
#define CHN (BB*NCH*DD*NN)

#define MM (BB*LL)      // 4096 rows
#define KC 1024         // concatenated K (2x512): [Xh|Xl] x [Wh|Wh]
#define NW 576          // widened N for fused dt+B+C gemm
#define NSCANBLK 512    // fused scan grid size

// Scratch
__device__ float g_dt[BLD];
__device__ float g_Bm[BLN];
__device__ float g_Cm[BLN];
__device__ float g_P[CHN];
__device__ float g_He[CHN];
__device__ float g_carry[CHN];
__device__ float g_beff[DD];
__device__ volatile unsigned g_barc[4];           // grid-barrier counters
__device__ __half g_Xcat0[(size_t)MM * KC];       // [Xh | Xl]
__device__ __half g_Xcat1[(size_t)MM * KC];       // z split (also temp Wlin2 split)
__device__ __half g_Wcat[5 * (size_t)NW * KC];    // slots: 0,1=Wdt; 2=Wlin0; 3=Wdec; 4=F

__device__ __forceinline__ float softplusf(float x) {
    return fmaxf(x, 0.f) + log1pf(__expf(-fabsf(x)));
}

__device__ __forceinline__ uint32_t smem_u32(const void* p) {
    uint32_t a;
    asm("{ .reg .u64 t; cvta.to.shared.u64 t, %1; cvt.u32.u64 %0, t; }" : "=r"(a) : "l"(p));
    return a;
}

__device__ __forceinline__ uint32_t swz(int r, int c) {
    return ((uint32_t)r << 7) + ((uint32_t)(c ^ (r & 7)) << 4);
}

// grid barrier (all NSCANBLK blocks co-resident by construction)
__device__ __forceinline__ void gridbar(int i) {
    __threadfence();
    __syncthreads();
    if (threadIdx.x == 0) {
        atomicAdd((unsigned*)&g_barc[i], 1u);
        while (g_barc[i] < NSCANBLK) {}
    }
    __syncthreads();
    __threadfence();
}

#define BK 64
#define STG 3
#define ABYTES 16384
#define BBYTES 8192
#define STAGE_BYTES (ABYTES + BBYTES)
#define TC_SMEM (STG * STAGE_BYTES)

// ---------------------------------------------------------------------------
// Shared GEMM mainloop macro (produces acc[2][4][4] for tile (bm, bn)).
// ---------------------------------------------------------------------------
#define GEMM_MAINLOOP(Aop, Bop)                                                              \
    extern __shared__ char smem[];                                                          \
    uint32_t sbase = smem_u32(smem);                                                        \
    int tid = threadIdx.x, wid = tid >> 5, lane = tid & 31;                                 \
    int wm = wid & 3, wn = wid >> 2;                                                        \
    int lrow = ((lane >> 3) & 1) * 8 + (lane & 7);                                          \
    int lck = lane >> 4;                                                                    \
    uint32_t aoff[2][4], boff[2][4];                                                        \
    _Pragma("unroll")                                                                       \
    for (int mt = 0; mt < 2; mt++)                                                          \
        _Pragma("unroll")                                                                   \
        for (int ks = 0; ks < 4; ks++)                                                      \
            aoff[mt][ks] = swz(wm * 32 + mt * 16 + lrow, ks * 2 + lck);                     \
    _Pragma("unroll")                                                                       \
    for (int nt = 0; nt < 2; nt++)                                                          \
        _Pragma("unroll")                                                                   \
        for (int ks = 0; ks < 4; ks++)                                                      \
            boff[nt][ks] = ABYTES + swz(wn * 32 + nt * 16 + lrow, ks * 2 + lck);            \
    int ra = tid >> 1, ca0 = (tid & 1) * 4;                                                 \
    int rb = tid >> 2, cb0 = (tid & 3) * 2;                                                 \
    const __half* gA = (Aop) + (size_t)(bm + ra) * KC + ca0 * 8;                            \
    const __half* gB = (Bop) + (size_t)(bn + rb) * KC + cb0 * 8;                            \
    uint32_t dA[4], dB[2];                                                                  \
    _Pragma("unroll")                                                                       \
    for (int i = 0; i < 4; i++) dA[i] = swz(ra, ca0 + i);                                   \
    _Pragma("unroll")                                                                       \
    for (int i = 0; i < 2; i++) dB[i] = ABYTES + swz(rb, cb0 + i);                          \
    float acc[2][4][4];                                                                     \
    _Pragma("unroll")                                                                       \
    for (int i = 0; i < 2; i++)                                                             \
        _Pragma("unroll")                                                                   \
        for (int j = 0; j < 4; j++)                                                         \
            _Pragma("unroll")                                                               \
            for (int q = 0; q < 4; q++) acc[i][j][q] = 0.f;                                 \
    const int NKB = KC / BK;                                                                \
    _Pragma("unroll")                                                                       \
    for (int s = 0; s < STG - 1; s++) {                                                     \
        uint32_t st = sbase + s * STAGE_BYTES;                                              \
        int ko = s * BK;                                                                    \
        _Pragma("unroll")                                                                   \
        for (int i = 0; i < 4; i++)                                                         \
            asm volatile("cp.async.cg.shared.global [%0], [%1], 16;"                        \
                         :: "r"(st + dA[i]), "l"(gA + ko + i * 8));                         \
        _Pragma("unroll")                                                                   \
        for (int i = 0; i < 2; i++)                                                         \
            asm volatile("cp.async.cg.shared.global [%0], [%1], 16;"                        \
                         :: "r"(st + dB[i]), "l"(gB + ko + i * 8));                         \
        asm volatile("cp.async.commit_group;" ::: "memory");                                \
    }                                                                                       \
    uint32_t bufA[2][2][4], bufB[2][2][4];                                                  \
    int sbuf = 0;                                                                           \
    for (int kb = 0; kb < NKB; kb++) {                                                      \
        asm volatile("cp.async.wait_group %0;" :: "n"(STG - 2) : "memory");                 \
        __syncthreads();                                                                    \
        int knext = kb + STG - 1;                                                           \
        if (knext < NKB) {                                                                  \
            int sn = knext % STG;                                                           \
            uint32_t st = sbase + sn * STAGE_BYTES;                                         \
            int ko = knext * BK;                                                            \
            _Pragma("unroll")                                                               \
            for (int i = 0; i < 4; i++)                                                     \
                asm volatile("cp.async.cg.shared.global [%0], [%1], 16;"                    \
                             :: "r"(st + dA[i]), "l"(gA + ko + i * 8));                     \
            _Pragma("unroll")                                                               \
            for (int i = 0; i < 2; i++)                                                     \
                asm volatile("cp.async.cg.shared.global [%0], [%1], 16;"                    \
                             :: "r"(st + dB[i]), "l"(gB + ko + i * 8));                     \
        }                                                                                   \
        asm volatile("cp.async.commit_group;" ::: "memory");                                \
        uint32_t st = sbase + sbuf * STAGE_BYTES;                                           \
        _Pragma("unroll")                                                                   \
        for (int mt = 0; mt < 2; mt++)                                                      \
            asm volatile("ldmatrix.sync.aligned.m8n8.x4.shared.b16 {%0,%1,%2,%3}, [%4];"    \
                         : "=r"(bufA[0][mt][0]), "=r"(bufA[0][mt][1]),                      \
                           "=r"(bufA[0][mt][2]), "=r"(bufA[0][mt][3])                       \
                         : "r"(st + aoff[mt][0]));                                          \
        _Pragma("unroll")                                                                   \
        for (int nt = 0; nt < 2; nt++)                                                      \
            asm volatile("ldmatrix.sync.aligned.m8n8.x4.shared.b16 {%0,%1,%2,%3}, [%4];"    \
                         : "=r"(bufB[0][nt][0]), "=r"(bufB[0][nt][1]),                      \
                           "=r"(bufB[0][nt][2]), "=r"(bufB[0][nt][3])                       \
                         : "r"(st + boff[nt][0]));                                          \
        _Pragma("unroll")                                                                   \
        for (int ks = 0; ks < 4; ks++) {                                                    \
            int cb = ks & 1, nb = cb ^ 1;                                                   \
            if (ks < 3) {                                                                   \
                _Pragma("unroll")                                                           \
                for (int mt = 0; mt < 2; mt++)                                              \
                    asm volatile("ldmatrix.sync.aligned.m8n8.x4.shared.b16 {%0,%1,%2,%3}, [%4];" \
                                 : "=r"(bufA[nb][mt][0]), "=r"(bufA[nb][mt][1]),            \
                                   "=r"(bufA[nb][mt][2]), "=r"(bufA[nb][mt][3])             \
                                 : "r"(st + aoff[mt][ks + 1]));                             \
                _Pragma("unroll")                                                           \
                for (int nt = 0; nt < 2; nt++)                                              \
                    asm volatile("ldmatrix.sync.aligned.m8n8.x4.shared.b16 {%0,%1,%2,%3}, [%4];" \
                                 : "=r"(bufB[nb][nt][0]), "=r"(bufB[nb][nt][1]),            \
                                   "=r"(bufB[nb][nt][2]), "=r"(bufB[nb][nt][3])             \
                                 : "r"(st + boff[nt][ks + 1]));                             \
            }                                                                               \
            _Pragma("unroll")                                                               \
            for (int mt = 0; mt < 2; mt++)                                                  \
                _Pragma("unroll")                                                           \
                for (int nt = 0; nt < 2; nt++)                                              \
                    _Pragma("unroll")                                                       \
                    for (int nf = 0; nf < 2; nf++)                                          \
                        asm volatile(                                                       \
                            "mma.sync.aligned.m16n8k16.row.col.f32.f16.f16.f32 "            \
                            "{%0,%1,%2,%3}, {%4,%5,%6,%7}, {%8,%9}, {%0,%1,%2,%3};"         \
                            : "+f"(acc[mt][nt * 2 + nf][0]), "+f"(acc[mt][nt * 2 + nf][1]), \
                              "+f"(acc[mt][nt * 2 + nf][2]), "+f"(acc[mt][nt * 2 + nf][3])  \
                            : "r"(bufA[cb][mt][0]), "r"(bufA[cb][mt][1]),                   \
                              "r"(bufA[cb][mt][2]), "r"(bufA[cb][mt][3]),                   \
                              "r"(bufB[cb][nt][nf]), "r"(bufB[cb][nt][2 + nf]));            \
        }                                                                                   \
        sbuf++;                                                                             \
        if (sbuf == STG) sbuf = 0;                                                          \
    }

// ---------------------------------------------------------------------------
// tc_gemm: EPI 0 = bias -> C float; EPI 1 = dt softplus + Bm/Cm fused;
// EPI 2 = bias + fp16-split to xout ONLY (no float C write).
// ---------------------------------------------------------------------------
template<int EPI>
__global__ void __launch_bounds__(256, 3)
tc_gemm(const __half* __restrict__ Ain, const __half* __restrict__ Bw,
        const float* __restrict__ bias, const float* __restrict__ bB,
        const float* __restrict__ bC, float* __restrict__ C,
        __half* __restrict__ xout)
{
    int bn = blockIdx.x * 64, bm = blockIdx.y * 128;
    GEMM_MAINLOOP(Ain, Bw)

    int mbase = bm + wm * 32 + (lane >> 2);
    int nbase = bn + wn * 32 + (lane & 3) * 2;
    #pragma unroll
    for (int mt = 0; mt < 2; mt++) {
        #pragma unroll
        for (int jf = 0; jf < 4; jf++) {
            int col = nbase + (jf >> 1) * 16 + (jf & 1) * 8;
            int m0 = mbase + mt * 16;
            float b0, b1;
            if (EPI == 1 && col >= 512) {
                if (col < 528)      { b0 = bB[col - 512]; b1 = bB[col - 511]; }
                else if (col < 544) { b0 = bC[col - 528]; b1 = bC[col - 527]; }
                else                { b0 = 0.f; b1 = 0.f; }
            } else {
                b0 = bias[col]; b1 = bias[col + 1];
            }
            float v0 = acc[mt][jf][0] + b0, v1 = acc[mt][jf][1] + b1;
            float v2 = acc[mt][jf][2] + b0, v3 = acc[mt][jf][3] + b1;

            if (EPI == 1 && col >= 512) {
                if (col < 528) {
                    int n = col - 512;
                    *(float2*)(g_Bm + (size_t)m0 * NN + n)       = make_float2(v0, v1);
                    *(float2*)(g_Bm + (size_t)(m0 + 8) * NN + n) = make_float2(v2, v3);
                } else if (col < 544) {
                    int n = col - 528;
                    *(float2*)(g_Cm + (size_t)m0 * NN + n)       = make_float2(v0, v1);
                    *(float2*)(g_Cm + (size_t)(m0 + 8) * NN + n) = make_float2(v2, v3);
                }
                continue;
            }
            if (EPI == 1) { v0 = softplusf(v0); v1 = softplusf(v1); v2 = softplusf(v2); v3 = softplusf(v3); }
            if (EPI != 2) {
                *(float2*)(C + (size_t)m0 * DD + col)       = make_float2(v0, v1);
                *(float2*)(C + (size_t)(m0 + 8) * DD + col) = make_float2(v2, v3);
            }
            if (EPI == 2) {
                __half h0 = __float2half_rn(v0), h1 = __float2half_rn(v1);
                __half h2 = __float2half_rn(v2), h3 = __float2half_rn(v3);
                __half2 hv0(h0, h1), hv1(h2, h3);
                __half2 lv0(__float2half_rn(v0 - __half2float(h0)),
                            __float2half_rn(v1 - __half2float(h1)));
                __half2 lv1(__float2half_rn(v2 - __half2float(h2)),
                            __float2half_rn(v3 - __half2float(h3)));
                __half* r0 = xout + (size_t)m0 * KC + col;
                __half* r1 = xout + (size_t)(m0 + 8) * KC + col;
                *(__half2*)(r0)        = hv0;
                *(__half2*)(r0 + 512)  = lv0;
                *(__half2*)(r1)        = hv1;
                *(__half2*)(r1 + 512)  = lv1;
            }
        }
    }
}

template __global__ void tc_gemm<0>(const __half*, const __half*, const float*,
                                    const float*, const float*, float*, __half*);
template __global__ void tc_gemm<1>(const __half*, const __half*, const float*,
                                    const float*, const float*, float*, __half*);
template __global__ void tc_gemm<2>(const __half*, const __half*, const float*,
                                    const float*, const float*, float*, __half*);

// ---------------------------------------------------------------------------
// Combo kernel: grid (9, 36). by<32: layer-0 dt GEMM (EPI1). by>=32 (bx<8):
// F = Wlin2 @ Wdec, epilogue writes transposed fp16 split directly to slot 4.
// ---------------------------------------------------------------------------
__global__ void __launch_bounds__(256, 3)
tc_gemm_combo(const float* __restrict__ bdt0, const float* __restrict__ bB0,
              const float* __restrict__ bC0)
{
    bool fm = (blockIdx.y >= 32);
    if (fm && blockIdx.x >= 8) return;
    int bn = blockIdx.x * 64;
    int bm = fm ? (int)(blockIdx.y - 32) * 128 : (int)blockIdx.y * 128;
    const __half* Aop = fm ? g_Xcat1 : g_Xcat0;
    const __half* Bop = g_Wcat + (size_t)(fm ? 3 : 0) * NW * KC;

    GEMM_MAINLOOP(Aop, Bop)

    int mbase = bm + wm * 32 + (lane >> 2);
    int nbase = bn + wn * 32 + (lane & 3) * 2;
    __half* slot4 = g_Wcat + (size_t)4 * NW * KC;

    #pragma unroll
    for (int mt = 0; mt < 2; mt++) {
        #pragma unroll
        for (int jf = 0; jf < 4; jf++) {
            int col = nbase + (jf >> 1) * 16 + (jf & 1) * 8;
            int m0 = mbase + mt * 16;
            if (fm) {
                #pragma unroll
                for (int q = 0; q < 4; q++) {
                    int mm = m0 + (q >> 1) * 8;
                    int cc = col + (q & 1);
                    __half h = __float2half_rn(acc[mt][jf][q]);
                    slot4[(size_t)cc * KC + mm]       = h;
                    slot4[(size_t)cc * KC + mm + 512] = h;
                }
                continue;
            }
            float b0, b1;
            if (col >= 512) {
                if (col < 528)      { b0 = bB0[col - 512]; b1 = bB0[col - 511]; }
                else if (col < 544) { b0 = bC0[col - 528]; b1 = bC0[col - 527]; }
                else                { b0 = 0.f; b1 = 0.f; }
            } else {
                b0 = bdt0[col]; b1 = bdt0[col + 1];
            }
            float v0 = acc[mt][jf][0] + b0, v1 = acc[mt][jf][1] + b1;
            float v2 = acc[mt][jf][2] + b0, v3 = acc[mt][jf][3] + b1;
            if (col >= 512) {
                if (col < 528) {
                    int n = col - 512;
                    *(float2*)(g_Bm + (size_t)m0 * NN + n)       = make_float2(v0, v1);
                    *(float2*)(g_Bm + (size_t)(m0 + 8) * NN + n) = make_float2(v2, v3);
                } else if (col < 544) {
                    int n = col - 528;
                    *(float2*)(g_Cm + (size_t)m0 * NN + n)       = make_float2(v0, v1);
                    *(float2*)(g_Cm + (size_t)(m0 + 8) * NN + n) = make_float2(v2, v3);
                }
                continue;
            }
            v0 = softplusf(v0); v1 = softplusf(v1); v2 = softplusf(v2); v3 = softplusf(v3);
            *(float2*)(g_dt + (size_t)m0 * DD + col)       = make_float2(v0, v1);
            *(float2*)(g_dt + (size_t)(m0 + 8) * DD + col) = make_float2(v2, v3);
        }
    }
}

// ---------------------------------------------------------------------------
// Merged prep kernel. grid (16, 16, 8), block 256.
// ---------------------------------------------------------------------------
__global__ void prep_k(const float* __restrict__ Wdt, const float* __restrict__ Wlin,
                       const float* __restrict__ Wdec, const float* __restrict__ WB,
                       const float* __restrict__ WC, const float* __restrict__ blin,
                       const float* __restrict__ bdec, const float4* __restrict__ x)
{
    __shared__ float t[32][33];
    __shared__ float part[32][8];
    int z = blockIdx.z;
    int bx = blockIdx.x, by = blockIdx.y;
    int tid = threadIdx.x;
    int tx = tid & 31, ty = tid >> 5;
    int bid = by * 16 + bx;

    if (z < 4) {
        const float* W = (z == 0) ? Wdt
                       : (z == 1) ? Wdt + (size_t)DD * DD
                       : (z == 2) ? Wlin
                                  : Wdec;
        __half* out = g_Wcat + (size_t)z * NW * KC;
        int bk = bx * 32, bn = by * 32;
        #pragma unroll
        for (int i = 0; i < 32; i += 8)
            t[ty + i][tx] = W[(size_t)(bk + ty + i) * DD + bn + tx];
        __syncthreads();
        #pragma unroll
        for (int i = 0; i < 32; i += 8) {
            float v = t[tx][ty + i];
            __half h = __float2half_rn(v);
            size_t o = (size_t)(bn + ty + i) * KC + bk + tx;
            out[o]       = h;
            out[o + 512] = h;
        }
    } else if (z == 4) {
        if (by >= 2) return;
        int l = by;
        int bk = bx * 32;
        __half* out = g_Wcat + (size_t)l * NW * KC + (size_t)512 * KC;
        for (int r = ty; r < 64; r += 8) {
            float v = 0.f;
            if (r < 16)      v = WB[(size_t)l * DD * NN + (size_t)(bk + tx) * NN + r];
            else if (r < 32) v = WC[(size_t)l * DD * NN + (size_t)(bk + tx) * NN + (r - 16)];
            __half h = __float2half_rn(v);
            size_t o = (size_t)r * KC + bk + tx;
            out[o]       = h;
            out[o + 512] = h;
        }
    } else if (z == 5) {
        const float4* in = (const float4*)(Wlin + (size_t)DD * DD);
        int i = bid * 256 + tid;
        int m = i >> 7;
        int k4 = (i & 127) << 2;
        float4 v = in[i];
        __half2 h0(__float2half_rn(v.x), __float2half_rn(v.y));
        __half2 h1(__float2half_rn(v.z), __float2half_rn(v.w));
        __half2 l0(__float2half_rn(v.x - __half2float(h0.x)),
                   __float2half_rn(v.y - __half2float(h0.y)));
        __half2 l1(__float2half_rn(v.z - __half2float(h1.x)),
                   __float2half_rn(v.w - __half2float(h1.y)));
        __half* row = g_Xcat1 + (size_t)m * KC;
        *(__half2*)(row + k4)       = h0;
        *(__half2*)(row + k4 + 2)   = h1;
        *(__half2*)(row + k4 + 512) = l0;
        *(__half2*)(row + k4 + 514) = l1;
    } else if (z == 6) {
        if (bid == 0 && tid < 4) g_barc[tid] = 0;
        if (bid >= 64) return;
        const float* blin2 = blin + DD;
        int og = tid & 7;
        int r  = tid >> 3;
        int o  = bid * 8 + og;
        float acc = 0.f;
        int d0 = r * 16;
        #pragma unroll
        for (int d = d0; d < d0 + 16; d++)
            acc = fmaf(blin2[d], Wdec[(size_t)d * DD + o], acc);
        part[r][og] = acc;
        __syncthreads();
        if (tid < 8) {
            float s = bdec[bid * 8 + tid];
            #pragma unroll
            for (int i = 0; i < 32; i++) s += part[i][tid];
            g_beff[bid * 8 + tid] = s;
        }
    } else {
        #pragma unroll
        for (int it = 0; it < 8; it++) {
            int i = (bid * 8 + it) * 256 + tid;
            int m = i >> 7;
            int k4 = (i & 127) << 2;
            float4 v = x[i];
            __half2 h0(__float2half_rn(v.x), __float2half_rn(v.y));
            __half2 h1(__float2half_rn(v.z), __float2half_rn(v.w));
            __half2 l0(__float2half_rn(v.x - __half2float(h0.x)),
                       __float2half_rn(v.y - __half2float(h0.y)));
            __half2 l1(__float2half_rn(v.z - __half2float(h1.x)),
                       __float2half_rn(v.w - __half2float(h1.y)));
            __half* row = g_Xcat0 + (size_t)m * KC;
            *(__half2*)(row + k4)       = h0;
            *(__half2*)(row + k4 + 2)   = h1;
            *(__half2*)(row + k4 + 512) = l0;
            *(__half2*)(row + k4 + 514) = l1;
        }
    }
}

// ---------------------------------------------------------------------------
// Fused scan: A (local scan) / barrier / B (chunk combine) / barrier /
// C (rescan+emit). If yhalf != nullptr, y is reconstructed from its [hi|lo]
// planes (layer 1); otherwise read float yin (layer 0).
// grid (4, NCH, BB) = 512 blocks, block 128.
// ---------------------------------------------------------------------------
__global__ void __launch_bounds__(128)
scan_fused_k(const float* __restrict__ yin, const __half* __restrict__ yhalf,
             const float* __restrict__ A, const float* __restrict__ Dskip, int barBase)
{
    __shared__ float sB[LCH * NN];
    __shared__ float sC[LCH * NN];
    int d = blockIdx.x * 128 + threadIdx.x;
    int c = blockIdx.y, b = blockIdx.z;
    int t0 = c * LCH;
    int fb = blockIdx.x + 4 * (blockIdx.y + NCH * blockIdx.z);

    {
        const float4* srcB = (const float4*)(g_Bm + ((size_t)b * LL + t0) * NN);
        const float4* srcC = (const float4*)(g_Cm + ((size_t)b * LL + t0) * NN);
        #pragma unroll
        for (int i = threadIdx.x; i < LCH * NN / 4; i += 128) {
            ((float4*)sB)[i] = srcB[i];
            ((float4*)sC)[i] = srcC[i];
        }
    }
    __syncthreads();

    float av[NN];
    #pragma unroll
    for (int q = 0; q < 4; q++)
        *(float4*)(av + q * 4) = *(const float4*)(A + (size_t)d * NN + q * 4);

    const float* dtp = g_dt + ((size_t)b * LL + t0) * DD + d;
    const float*  ypf = yin   ? yin   + ((size_t)b * LL + t0) * DD + d : nullptr;
    const __half* yph = yhalf ? yhalf + ((size_t)b * LL + t0) * KC + d : nullptr;

    // ---- phase A ----
    {
        float h[NN], p[NN];
        #pragma unroll
        for (int n = 0; n < NN; n++) { h[n] = 0.f; p[n] = 1.f; }
        for (int t = 0; t < LCH; t++) {
            float dv = dtp[(size_t)t * DD];
            float yv = yph ? (__half2float(yph[(size_t)t * KC]) + __half2float(yph[(size_t)t * KC + 512]))
                           : ypf[(size_t)t * DD];
            float u  = dv * yv;
            #pragma unroll
            for (int n = 0; n < NN; n++) {
                float e = __expf(dv * av[n]);
                p[n] *= e;
                h[n] = fmaf(e, h[n], u * sB[t * NN + n]);
            }
        }
        size_t o = (((size_t)b * NCH + c) * DD + d) * NN;
        #pragma unroll
        for (int q = 0; q < 4; q++) {
            *(float4*)(g_P  + o + q * 4) = *(float4*)(p + q * 4);
            *(float4*)(g_He + o + q * 4) = *(float4*)(h + q * 4);
        }
    }

    gridbar(barBase);

    // ---- phase B ----
    if (fb < 256) {
        int idx = fb * 128 + threadIdx.x;
        int bb = idx >> 13;
        int dn = idx & 8191;
        size_t base = (size_t)bb * NCH * DD * NN + dn;
        float hc = 0.f;
        for (int g = 0; g < NCH; g += 8) {
            float p[8], he[8];
            #pragma unroll
            for (int j = 0; j < 8; j++) {
                p[j]  = g_P [base + (size_t)(g + j) * DD * NN];
                he[j] = g_He[base + (size_t)(g + j) * DD * NN];
            }
            #pragma unroll
            for (int j = 0; j < 8; j++) {
                g_carry[base + (size_t)(g + j) * DD * NN] = hc;
                hc = fmaf(p[j], hc, he[j]);
            }
        }
    }

    gridbar(barBase + 1);

    // ---- phase C ----
    {
        float h[NN];
        size_t co = (((size_t)b * NCH + c) * DD + d) * NN;
        #pragma unroll
        for (int q = 0; q < 4; q++)
            *(float4*)(h + q * 4) = *(const float4*)(g_carry + co + q * 4);

        float ds = Dskip[d];
        __half* zb = g_Xcat1 + ((size_t)b * LL + t0) * KC + d;
        for (int t = 0; t < LCH; t++) {
            float dv = dtp[(size_t)t * DD];
            float yv = yph ? (__half2float(yph[(size_t)t * KC]) + __half2float(yph[(size_t)t * KC + 512]))
                           : ypf[(size_t)t * DD];
            float u  = dv * yv;
            float acc = 0.f;
            #pragma unroll
            for (int n = 0; n < NN; n++) {
                float e = __expf(dv * av[n]);
                h[n] = fmaf(e, h[n], u * sB[t * NN + n]);
                acc = fmaf(h[n], sC[t * NN + n], acc);
            }
            float z = fmaxf(fmaf(ds, yv, acc), 0.f);
            __half hi = __float2half_rn(z);
            __half lo = __float2half_rn(z - __half2float(hi));
            __half* zr = zb + (size_t)t * KC;
            zr[0]   = hi;
            zr[512] = lo;
        }
    }
}

// ---------------------------------------------------------------------------
// Host launcher (7 graph nodes)
// ---------------------------------------------------------------------------
extern "C" void kernel_launch(void* const* d_in, const int* in_sizes, int n_in,
                              void* d_out, int out_size)
{
    const float* x     = (const float*)d_in[0];
    const float* A     = (const float*)d_in[1];
    const float* Dskip = (const float*)d_in[2];
    const float* WB    = (const float*)d_in[3];
    const float* bB    = (const float*)d_in[4];
    const float* WC    = (const float*)d_in[5];
    const float* bC    = (const float*)d_in[6];
    const float* Wdt   = (const float*)d_in[7];
    const float* bdt   = (const float*)d_in[8];
    const float* Wlin  = (const float*)d_in[9];
    const float* blin  = (const float*)d_in[10];
    const float* Wdec  = (const float*)d_in[11];
    const float* bdec  = (const float*)d_in[12];
    float* out = (float*)d_out;

    float *pdt, *pbeff;
    __half *px0, *px1, *pwc;
    cudaGetSymbolAddress((void**)&pdt,   g_dt);
    cudaGetSymbolAddress((void**)&pbeff, g_beff);
    cudaGetSymbolAddress((void**)&px0,   g_Xcat0);
    cudaGetSymbolAddress((void**)&px1,   g_Xcat1);
    cudaGetSymbolAddress((void**)&pwc,   g_Wcat);

    cudaFuncSetAttribute(tc_gemm<0>, cudaFuncAttributeMaxDynamicSharedMemorySize, TC_SMEM);
    cudaFuncSetAttribute(tc_gemm<1>, cudaFuncAttributeMaxDynamicSharedMemorySize, TC_SMEM);
    cudaFuncSetAttribute(tc_gemm<2>, cudaFuncAttributeMaxDynamicSharedMemorySize, TC_SMEM);
    cudaFuncSetAttribute(tc_gemm_combo, cudaFuncAttributeMaxDynamicSharedMemorySize, TC_SMEM);

    const size_t WCSZ = (size_t)NW * KC;

    dim3 gG1(NW / 64, MM / 128);    // (9, 32)
    dim3 gG(DD / 64, MM / 128);     // (8, 32)
    dim3 gsc(DD / 128, NCH, BB);    // 512 blocks

    // 1) prep
    prep_k<<<dim3(16, 16, 8), 256>>>(Wdt, Wlin, Wdec, WB, WC, blin, bdec, (const float4*)x);

    // 2) layer-0 dt GEMM + fused-F GEMM
    tc_gemm_combo<<<dim3(9, 36), 256, TC_SMEM>>>(bdt, bB, bC);

    // 3) layer-0 fused scan (y = input x, float)
    scan_fused_k<<<gsc, 128>>>(x, nullptr, A, Dskip, 0);

    // 4) layer-0 lin GEMM: fp16-split epilogue only -> Xcat0
    tc_gemm<2><<<gG, 256, TC_SMEM>>>(px1, pwc + 2 * WCSZ, blin,
                                     nullptr, nullptr, nullptr, px0);

    // 5) layer-1 dt GEMM (fused Bm/Cm)
    tc_gemm<1><<<gG1, 256, TC_SMEM>>>(px0, pwc + 1 * WCSZ, bdt + DD,
                                      bB + NN, bC + NN, pdt, nullptr);

    // 6) layer-1 fused scan (y reconstructed from Xcat0 halves)
    scan_fused_k<<<gsc, 128>>>(nullptr, px0, A + (size_t)DD * NN, Dskip + DD, 2);

    // 7) fused lin2+dec: out = z2 @ F + beff
    tc_gemm<0><<<gG, 256, TC_SMEM>>>(px1, pwc + 4 * WCSZ, pbeff,
                                     nullptr, nullptr, out, nullptr);
}